// round 9
// baseline (speedup 1.0000x reference)
#include <cuda_runtime.h>
#include <cuda_bf16.h>
#include <cstdint>

#define D_FIX 512
#define NR 32768
#define KP 8192
#define CTA_M 128
#define CTA_N 128
#define NCHQ 16                // k tiles of 32 int8
#define NSTEP 8                // pipeline chunks of k64 (2 tiles)
#define RBLK (NR/CTA_M)        // 256
#define CBLK (KP/CTA_N)        // 64
#define NGRP (KP/8)            // 1024 groups of 8 cols
#define TILE_U 256             // 16B units per 4KB k32-int8 tile (128 rows)
#define SMEM_STAGES (4*16384)  // 4 stages x 16KB (A 8KB + B 8KB)
#define SMEM_TOTAL  (SMEM_STAGES + 2048)
#define MARGIN 1e-3f
#define WCAP (1u<<22)

// ---- device-global scratch (allocations forbidden) ----
__device__ uint4  g_A[(size_t)RBLK * NCHQ * TILE_U];     // 16MB int8 quantized
__device__ uint4  g_B[(size_t)CBLK * NCHQ * TILE_U];     // 4MB
__device__ float  g_xnorm[NR];
__device__ float  g_pnorm[KP];
__device__ float  g_xq[NR];    // quant scale 127/max
__device__ float  g_pq[KP];
__device__ float  g_xr[NR];    // dequant step max/127
__device__ float  g_pr[KP];
__device__ float  g_gmin[(size_t)NGRP * NR];             // 128MB [group][row]
__device__ float  g_rowthr[NR];
__device__ unsigned long long g_bestkey[NR];
__device__ unsigned int g_wcount;
__device__ unsigned int g_wlist[WCAP];
__device__ double g_losspart[NR];
__device__ double g_losspart2[128];

// ---------------- PTX helpers (baseline sm_80-class only) ----------------
__device__ __forceinline__ uint32_t smem_u32(const void* p) {
    uint32_t a;
    asm("{ .reg .u64 t; cvta.to.shared.u64 t, %1; cvt.u32.u64 %0, t; }" : "=r"(a) : "l"(p));
    return a;
}
__device__ __forceinline__ void cp16(uint32_t dst, const void* src) {
    asm volatile("cp.async.cg.shared.global [%0], [%1], 16;" :: "r"(dst), "l"(src));
}
#define CP_COMMIT() asm volatile("cp.async.commit_group;")
#define CP_WAIT2()  asm volatile("cp.async.wait_group 2;")

#define LDSM4(r0, r1, r2, r3, addr) \
    asm volatile("ldmatrix.sync.aligned.m8n8.x4.shared.b16 {%0,%1,%2,%3}, [%4];" \
        : "=r"(r0), "=r"(r1), "=r"(r2), "=r"(r3) : "r"(addr))

// s8 IMMA, s32 accumulate. Fragment byte layout == bf16 m16n8k16 layout.
#define MMAI(c, a, b) \
    asm volatile("mma.sync.aligned.m16n8k32.row.col.s32.s8.s8.s32 " \
        "{%0,%1,%2,%3}, {%4,%5,%6,%7}, {%8,%9}, {%0,%1,%2,%3};" \
        : "+r"((c)[0]), "+r"((c)[1]), "+r"((c)[2]), "+r"((c)[3]) \
        : "r"((a)[0]), "r"((a)[1]), "r"((a)[2]), "r"((a)[3]), \
          "r"((b)[0]), "r"((b)[1]))

// ---------------------------------------------------------------------------
// Kernel 1: row norms (double, one fp32 round — identical to R1) + per-row
// max|v| -> int8 quant scale (127/max) and dequant step (max/127).
// ---------------------------------------------------------------------------
__global__ void norms_kernel(const float* __restrict__ X, const float* __restrict__ P) {
    int row = blockIdx.x;
    const float* src = (row < NR) ? (X + (size_t)row * D_FIX)
                                  : (P + (size_t)(row - NR) * D_FIX);
    int t = threadIdx.x;
    double s = 0.0;
    float m = 0.0f;
#pragma unroll
    for (int i = 0; i < 4; ++i) {
        float v = src[t + i * 128];
        s += (double)v * (double)v;
        m = fmaxf(m, fabsf(v));
    }
#pragma unroll
    for (int o = 16; o > 0; o >>= 1) {
        s += __shfl_down_sync(0xffffffffu, s, o);
        m = fmaxf(m, __shfl_down_sync(0xffffffffu, m, o));
    }
    __shared__ double sh[4];
    __shared__ float shm[4];
    if ((t & 31) == 0) { sh[t >> 5] = s; shm[t >> 5] = m; }
    __syncthreads();
    if (t == 0) {
        float r = (float)(sh[0] + sh[1] + sh[2] + sh[3]);
        float mx = fmaxf(fmaxf(shm[0], shm[1]), fmaxf(shm[2], shm[3]));
        float qs = 127.0f / mx;
        float rs = mx * (1.0f / 127.0f);
        if (row < NR) { g_xnorm[row] = r; g_xq[row] = qs; g_xr[row] = rs; }
        else { int k = row - NR; g_pnorm[k] = r; g_pq[k] = qs; g_pr[k] = rs; }
    }
}

// ---------------------------------------------------------------------------
// Kernel 2: int8 quantize, pre-swizzled tiled layout.
// Tile = 128 rows x 32 int8 (4KB); unit(r,h) = r*2 + (h ^ ((r>>2)&1)).
// ---------------------------------------------------------------------------
__global__ void prep_kernel(const float* __restrict__ X, const float* __restrict__ P) {
    if (blockIdx.x == 0 && threadIdx.x == 0) g_wcount = 0;
    int gid = blockIdx.x * 256 + threadIdx.x;
    const int xcnt = NR * NCHQ;
    bool isX = gid < xcnt;
    int g = isX ? gid : gid - xcnt;
    int row, chunk;
    if (isX) { row = g & (NR - 1); chunk = g >> 15; }
    else     { row = g & (KP - 1); chunk = g >> 13; }
    const float4* src = (const float4*)((isX ? X : P) + (size_t)row * D_FIX + chunk * 32);
    float qs = isX ? g_xq[row] : g_pq[row];

    unsigned int w[8];
#pragma unroll
    for (int i = 0; i < 8; i++) {
        float4 v = src[i];
        int b0 = __float2int_rn(v.x * qs);
        int b1 = __float2int_rn(v.y * qs);
        int b2 = __float2int_rn(v.z * qs);
        int b3 = __float2int_rn(v.w * qs);
        w[i] = (b0 & 0xFF) | ((b1 & 0xFF) << 8) | ((b2 & 0xFF) << 16)
             | ((unsigned)(b3 & 0xFF) << 24);
    }
    int rin = row & 127;
    int blk = row >> 7;
    size_t base = (size_t)(blk * NCHQ + chunk) * TILE_U;
    int swz = (rin >> 2) & 1;
    uint4* dst = isX ? g_A : g_B;
    uint4 u0 = make_uint4(w[0], w[1], w[2], w[3]);
    uint4 u1 = make_uint4(w[4], w[5], w[6], w[7]);
    dst[base + rin * 2 + (0 ^ swz)] = u0;
    dst[base + rin * 2 + (1 ^ swz)] = u1;
}

// ---------------------------------------------------------------------------
// Kernel 3: IMMA s8 GEMM 128x128 + per-8col-group min epilogue.
// 8 warps (2m x 4n), 4-stage cp.async pipeline, k64 chunks (2 k32 subtiles).
// Swizzle/ldmatrix addressing identical to validated bf16 path.
// ---------------------------------------------------------------------------
__device__ __forceinline__ void issue_stage(uint32_t sbase, int s, int tid,
                                            const uint4* aSrc, const uint4* bSrc) {
    uint32_t dst = sbase + (uint32_t)(s & 3) * 16384;
#pragma unroll
    for (int i = 0; i < 4; i++) {
        int u = tid + i * 256;
        const uint4* src = (u < 512) ? (aSrc + (size_t)s * 512 + u)
                                     : (bSrc + (size_t)s * 512 + (u - 512));
        cp16(dst + u * 16, src);
    }
}

__global__ __launch_bounds__(256, 2) void gemm_gmin_kernel() {
    extern __shared__ char smem[];
    uint32_t sb = smem_u32(smem);
    float* sAn = (float*)(smem + SMEM_STAGES);
    float* sAr = (float*)(smem + SMEM_STAGES + 512);
    float* sPn = (float*)(smem + SMEM_STAGES + 1024);
    float* sPr = (float*)(smem + SMEM_STAGES + 1536);

    const int tid = threadIdx.x;
    const int colblk = blockIdx.x & (CBLK - 1);
    const int rowblk = blockIdx.x >> 6;
    const int wid = tid >> 5, lane = tid & 31;
    const int wm = wid >> 2, wn = wid & 3;

    if (tid < 128) {
        sAn[tid] = g_xnorm[rowblk * CTA_M + tid];
        sAr[tid] = g_xr[rowblk * CTA_M + tid];
        sPn[tid] = g_pnorm[colblk * CTA_N + tid];
        sPr[tid] = g_pr[colblk * CTA_N + tid];
    }

    const uint4* aSrc = g_A + (size_t)rowblk * NCHQ * TILE_U;
    const uint4* bSrc = g_B + (size_t)colblk * NCHQ * TILE_U;

    issue_stage(sb, 0, tid, aSrc, bSrc); CP_COMMIT();
    issue_stage(sb, 1, tid, aSrc, bSrc); CP_COMMIT();
    issue_stage(sb, 2, tid, aSrc, bSrc); CP_COMMIT();

    int c[4][4][4];
#pragma unroll
    for (int i = 0; i < 4; i++)
#pragma unroll
        for (int j = 0; j < 4; j++)
#pragma unroll
            for (int v = 0; v < 4; v++) c[i][j][v] = 0;

    const int a_r = lane & 15;
    const int a_h = lane >> 4;
    const int b_r = (lane & 7) + ((lane >> 4) << 3);
    const int b_h = (lane >> 3) & 1;

    for (int s = 0; s < NSTEP; s++) {
        CP_WAIT2();
        __syncthreads();
        if (s + 3 < NSTEP) issue_stage(sb, s + 3, tid, aSrc, bSrc);
        CP_COMMIT();

        uint32_t stg = sb + (uint32_t)(s & 3) * 16384;
#pragma unroll
        for (int t = 0; t < 2; t++) {
            uint32_t sA = stg + t * 4096;
            uint32_t sB = stg + 8192 + t * 4096;

            uint32_t bf[4][2];
#pragma unroll
            for (int jj = 0; jj < 2; jj++) {
                int nrow = wn * 32 + jj * 16 + b_r;
                uint32_t addr = sB + nrow * 32 + ((b_h ^ ((nrow >> 2) & 1)) << 4);
                uint32_t r0, r1, r2, r3;
                LDSM4(r0, r1, r2, r3, addr);
                bf[jj * 2][0] = r0; bf[jj * 2][1] = r1;
                bf[jj * 2 + 1][0] = r2; bf[jj * 2 + 1][1] = r3;
            }
            uint32_t af[4][4];
#pragma unroll
            for (int i = 0; i < 4; i++) {
                int arow = wm * 64 + i * 16 + a_r;
                uint32_t addr = sA + arow * 32 + ((a_h ^ ((arow >> 2) & 1)) << 4);
                LDSM4(af[i][0], af[i][1], af[i][2], af[i][3], addr);
            }
#pragma unroll
            for (int i = 0; i < 4; i++)
#pragma unroll
                for (int j = 0; j < 4; j++)
                    MMAI(c[i][j], af[i], bf[j]);
        }
    }

    // ---- epilogue: dequant + per (row, 8-col group) min of approx dist ----
    const int q = lane >> 2;
#pragma unroll
    for (int i = 0; i < 4; i++) {
        int r0 = wm * 64 + i * 16 + q;
        float an0 = sAn[r0], an1 = sAn[r0 + 8];
        float rx0 = -2.0f * sAr[r0], rx1 = -2.0f * sAr[r0 + 8];
#pragma unroll
        for (int j = 0; j < 4; j++) {
            int c0 = wn * 32 + j * 8 + (lane & 3) * 2;
            float pn0 = sPn[c0], pn1 = sPn[c0 + 1];
            float rp0 = sPr[c0], rp1 = sPr[c0 + 1];
            float d00 = __fmaf_rn((float)c[i][j][0], rx0 * rp0, __fadd_rn(an0, pn0));
            float d01 = __fmaf_rn((float)c[i][j][1], rx0 * rp1, __fadd_rn(an0, pn1));
            float d10 = __fmaf_rn((float)c[i][j][2], rx1 * rp0, __fadd_rn(an1, pn0));
            float d11 = __fmaf_rn((float)c[i][j][3], rx1 * rp1, __fadd_rn(an1, pn1));
            float m0 = fminf(d00, d01);
            float m1 = fminf(d10, d11);
#pragma unroll
            for (int o = 1; o <= 2; o <<= 1) {
                m0 = fminf(m0, __shfl_xor_sync(0xffffffffu, m0, o));
                m1 = fminf(m1, __shfl_xor_sync(0xffffffffu, m1, o));
            }
            if ((lane & 3) == 0) {
                size_t gidx = (size_t)(colblk * 16 + wn * 4 + j) * NR
                            + rowblk * CTA_M + wm * 64 + i * 16;
                g_gmin[gidx + q] = m0;
                g_gmin[gidx + q + 8] = m1;
            }
        }
    }
}

// ---------------------------------------------------------------------------
// Kernel 4a: per-row min over 1024 group-mins (parallel, coalesced).
// ---------------------------------------------------------------------------
__global__ void rowmin_kernel() {
    int tid = threadIdx.x;
    int r = blockIdx.x * 64 + (tid & 63);
    int gl = tid >> 6;
    const float* col = g_gmin + (size_t)gl * 256 * NR + r;
    float mn = 3.402823466e38f;
    for (int g = 0; g < 256; g += 4) {
        float v0 = col[(size_t)(g + 0) * NR];
        float v1 = col[(size_t)(g + 1) * NR];
        float v2 = col[(size_t)(g + 2) * NR];
        float v3 = col[(size_t)(g + 3) * NR];
        mn = fminf(mn, fminf(fminf(v0, v1), fminf(v2, v3)));
    }
    __shared__ float sm[4][64];
    sm[gl][tid & 63] = mn;
    __syncthreads();
    if (tid < 64) {
        float m = fminf(fminf(sm[0][tid], sm[1][tid]), fminf(sm[2][tid], sm[3][tid]));
        int row = blockIdx.x * 64 + tid;
        g_rowthr[row] = m + MARGIN;
        g_bestkey[row] = 0xFFFFFFFFFFFFFFFFull;
    }
}

// ---------------------------------------------------------------------------
// Kernel 4b: flag groups within margin -> worklist.
// ---------------------------------------------------------------------------
__global__ void flag_kernel() {
    int tid = threadIdx.x;
    int r = blockIdx.x * 64 + (tid & 63);
    int gl = tid >> 6;
    float thr = g_rowthr[r];
    const float* col = g_gmin + (size_t)gl * 256 * NR + r;
    for (int g = 0; g < 256; g += 4) {
        float v0 = col[(size_t)(g + 0) * NR];
        float v1 = col[(size_t)(g + 1) * NR];
        float v2 = col[(size_t)(g + 2) * NR];
        float v3 = col[(size_t)(g + 3) * NR];
#pragma unroll
        for (int o = 0; o < 4; o++) {
            float v = (o == 0) ? v0 : (o == 1) ? v1 : (o == 2) ? v2 : v3;
            if (v <= thr) {
                unsigned int idx = atomicAdd(&g_wcount, 1u);
                if (idx < WCAP)
                    g_wlist[idx] = (unsigned)(r * NGRP + gl * 256 + g + o);
            }
        }
    }
}

// ---------------------------------------------------------------------------
// Kernel 5: exact rescore of flagged groups — identical numerics to R1/R5.
// ---------------------------------------------------------------------------
__global__ void rescore_kernel(const float* __restrict__ X, const float* __restrict__ P) {
    unsigned int count = g_wcount;
    if (count > WCAP) count = WCAP;
    for (unsigned int e = blockIdx.x * 256 + threadIdx.x; e < count;
         e += gridDim.x * 256) {
        unsigned int w = g_wlist[e];
        int row = (int)(w >> 10);
        int grp = (int)(w & (NGRP - 1));
        int k0 = grp * 8;
        const float4* x4 = (const float4*)(X + (size_t)row * D_FIX);
        const float4* p4 = (const float4*)(P + (size_t)k0 * D_FIX);
        float acc[8];
#pragma unroll
        for (int c = 0; c < 8; c++) acc[c] = 0.0f;
        for (int d = 0; d < D_FIX / 4; d++) {
            float4 xv = x4[d];
#pragma unroll
            for (int c = 0; c < 8; c++) {
                float4 pv = p4[(size_t)c * (D_FIX / 4) + d];
                acc[c] = __fmaf_rn(xv.x, pv.x, acc[c]);
                acc[c] = __fmaf_rn(xv.y, pv.y, acc[c]);
                acc[c] = __fmaf_rn(xv.z, pv.z, acc[c]);
                acc[c] = __fmaf_rn(xv.w, pv.w, acc[c]);
            }
        }
        float an = g_xnorm[row];
        unsigned long long best = 0xFFFFFFFFFFFFFFFFull;
#pragma unroll
        for (int c = 0; c < 8; c++) {
            float t = __fadd_rn(an, g_pnorm[k0 + c]);
            float d = __fadd_rn(t, __fmul_rn(-2.0f, acc[c]));
            unsigned long long key =
                ((unsigned long long)__float_as_uint(d) << 32) | (unsigned)(k0 + c);
            if (key < best) best = key;
        }
        atomicMin(&g_bestkey[row], best);
    }
}

// ---------------------------------------------------------------------------
// Kernel 6: gather + exact straight-through output + per-row loss partials.
// ---------------------------------------------------------------------------
__global__ void gather_loss_kernel(const float* __restrict__ X,
                                   const float* __restrict__ P,
                                   float* __restrict__ out) {
    int row = blockIdx.x;
    int t = threadIdx.x;
    int c = (int)(unsigned)(g_bestkey[row] & 0xFFFFFFFFull);
    const float* x = X + (size_t)row * D_FIX;
    const float* q = P + (size_t)c * D_FIX;
    float* o = out + (size_t)row * D_FIX;
    double s = 0.0;
#pragma unroll
    for (int i = 0; i < 4; i++) {
        int d = t + i * 128;
        float xv = x[d], qv = q[d];
        float diff = __fsub_rn(qv, xv);
        o[d] = __fadd_rn(xv, diff);
        s += (double)diff * (double)diff;
    }
#pragma unroll
    for (int o2 = 16; o2 > 0; o2 >>= 1) s += __shfl_down_sync(0xffffffffu, s, o2);
    __shared__ double sh[4];
    if ((t & 31) == 0) sh[t >> 5] = s;
    __syncthreads();
    if (t == 0) g_losspart[row] = sh[0] + sh[1] + sh[2] + sh[3];
}

// ---------------------------------------------------------------------------
// Kernel 7a: partial loss sums. 7b: final loss.
// ---------------------------------------------------------------------------
__global__ void losssum_kernel() {
    __shared__ double sh[256];
    int t = threadIdx.x;
    sh[t] = g_losspart[blockIdx.x * 256 + t];
    __syncthreads();
    for (int o = 128; o > 0; o >>= 1) {
        if (t < o) sh[t] += sh[t + o];
        __syncthreads();
    }
    if (t == 0) g_losspart2[blockIdx.x] = sh[0];
}

__global__ void finalize_kernel(float* __restrict__ out,
                                long long tail_start, long long out_sz) {
    __shared__ double sh[128];
    int t = threadIdx.x;
    sh[t] = g_losspart2[t];
    __syncthreads();
    for (int o = 64; o > 0; o >>= 1) {
        if (t < o) sh[t] += sh[t + o];
        __syncthreads();
    }
    if (t == 0) {
        double mean = sh[0] / ((double)NR * (double)D_FIX);
        float m = (float)mean;
        float v = __fadd_rn(__fmul_rn(m, 0.25f), m);
        for (long long i = tail_start; i < out_sz; ++i) out[i] = v;
    }
}

// ---------------------------------------------------------------------------
extern "C" void kernel_launch(void* const* d_in, const int* in_sizes, int n_in,
                              void* d_out, int out_size) {
    const float* X = (const float*)d_in[0];
    const float* P = (const float*)d_in[1];
    float* out = (float*)d_out;

    cudaFuncSetAttribute(gemm_gmin_kernel,
                         cudaFuncAttributeMaxDynamicSharedMemorySize, SMEM_TOTAL);

    norms_kernel<<<NR + KP, 128>>>(X, P);                       // scales first
    prep_kernel<<<(NR * NCHQ + KP * NCHQ) / 256, 256>>>(X, P);  // int8 quantize
    gemm_gmin_kernel<<<RBLK * CBLK, 256, SMEM_TOTAL>>>();
    rowmin_kernel<<<NR / 64, 256>>>();
    flag_kernel<<<NR / 64, 256>>>();
    rescore_kernel<<<1024, 256>>>(X, P);
    gather_loss_kernel<<<NR, 128>>>(X, P, out);
    losssum_kernel<<<128, 256>>>();
    finalize_kernel<<<1, 128>>>(out, (long long)NR * D_FIX, (long long)out_size);
}

// round 10
// speedup vs baseline: 1.1621x; 1.1621x over previous
#include <cuda_runtime.h>
#include <cuda_fp16.h>
#include <cstdint>

#define D_FIX 512
#define NR 32768
#define KP 8192
#define CTA_M 128
#define CTA_N 128
#define NCH16 32               // k tiles of 16
#define NCH32 16               // pipeline chunks of k32
#define RBLK (NR/CTA_M)        // 256
#define CBLK (KP/CTA_N)        // 64
#define NGRP (KP/8)            // 1024 groups of 8 cols
#define TILE_U 256             // 16B units per 4KB k16 tile
#define SMEM_STAGES (4*16384)  // 4 stages x 16KB (A 8KB + B 8KB)
#define SMEM_TOTAL  (SMEM_STAGES + 512 + 512)
#define MARGIN 2e-3f
#define WCAP (1u<<22)

// ---- device-global scratch (allocations forbidden) ----
__device__ uint4  g_A[(size_t)RBLK * NCH16 * TILE_U];    // 32MB f16
__device__ uint4  g_B[(size_t)CBLK * NCH16 * TILE_U];    // 8MB
__device__ float  g_xnorm[NR];
__device__ float  g_pnorm[KP];
__device__ float  g_gmin[(size_t)NGRP * NR];             // 128MB [group][row]
__device__ float  g_rowthr[NR];
__device__ unsigned long long g_bestkey[NR];
__device__ unsigned int g_wcount;
__device__ unsigned int g_wlist[WCAP];
__device__ double g_losspart[NR];
__device__ double g_losspart2[128];

// ---------------- PTX helpers (baseline sm_80-class only) ----------------
__device__ __forceinline__ uint32_t smem_u32(const void* p) {
    uint32_t a;
    asm("{ .reg .u64 t; cvta.to.shared.u64 t, %1; cvt.u32.u64 %0, t; }" : "=r"(a) : "l"(p));
    return a;
}
__device__ __forceinline__ void cp16(uint32_t dst, const void* src) {
    asm volatile("cp.async.cg.shared.global [%0], [%1], 16;" :: "r"(dst), "l"(src));
}
#define CP_COMMIT() asm volatile("cp.async.commit_group;")
#define CP_WAIT2()  asm volatile("cp.async.wait_group 2;")

#define LDSM4(r0, r1, r2, r3, addr) \
    asm volatile("ldmatrix.sync.aligned.m8n8.x4.shared.b16 {%0,%1,%2,%3}, [%4];" \
        : "=r"(r0), "=r"(r1), "=r"(r2), "=r"(r3) : "r"(addr))

// f16 HMMA with f16 accumulate: C/D = 2 regs (4 halves). Same A/B layout as bf16.
#define MMAH(c, a, b) \
    asm volatile("mma.sync.aligned.m16n8k16.row.col.f16.f16.f16.f16 " \
        "{%0,%1}, {%2,%3,%4,%5}, {%6,%7}, {%0,%1};" \
        : "+r"((c)[0]), "+r"((c)[1]) \
        : "r"((a)[0]), "r"((a)[1]), "r"((a)[2]), "r"((a)[3]), \
          "r"((b)[0]), "r"((b)[1]))

// ---------------------------------------------------------------------------
// Kernel 1: f16 convert, pre-swizzled tiled layout (layout validated R5-R8).
// unit(r, half) = r*2 + (half ^ ((r>>2)&1))  — conflict-free for ldmatrix.
// ---------------------------------------------------------------------------
__global__ void prep_kernel(const float* __restrict__ X, const float* __restrict__ P) {
    if (blockIdx.x == 0 && threadIdx.x == 0) g_wcount = 0;
    int gid = blockIdx.x * 256 + threadIdx.x;
    const int xcnt = NR * NCH16;
    bool isX = gid < xcnt;
    int g = isX ? gid : gid - xcnt;
    int row, chunk;
    if (isX) { row = g & (NR - 1); chunk = g >> 15; }
    else     { row = g & (KP - 1); chunk = g >> 13; }
    const float4* src = (const float4*)((isX ? X : P) + (size_t)row * D_FIX + chunk * 16);

    unsigned short hv[16];
#pragma unroll
    for (int i = 0; i < 4; i++) {
        float4 v = src[i];
        hv[i * 4 + 0] = __half_as_ushort(__float2half_rn(v.x));
        hv[i * 4 + 1] = __half_as_ushort(__float2half_rn(v.y));
        hv[i * 4 + 2] = __half_as_ushort(__float2half_rn(v.z));
        hv[i * 4 + 3] = __half_as_ushort(__float2half_rn(v.w));
    }
    int rin = row & 127;
    int blk = row >> 7;
    size_t base = (size_t)(blk * NCH16 + chunk) * TILE_U;
    int swz = (rin >> 2) & 1;
    uint4* dst = isX ? g_A : g_B;
    uint4 u0, u1;
    u0.x = hv[0]  | ((uint32_t)hv[1]  << 16);
    u0.y = hv[2]  | ((uint32_t)hv[3]  << 16);
    u0.z = hv[4]  | ((uint32_t)hv[5]  << 16);
    u0.w = hv[6]  | ((uint32_t)hv[7]  << 16);
    u1.x = hv[8]  | ((uint32_t)hv[9]  << 16);
    u1.y = hv[10] | ((uint32_t)hv[11] << 16);
    u1.z = hv[12] | ((uint32_t)hv[13] << 16);
    u1.w = hv[14] | ((uint32_t)hv[15] << 16);
    dst[base + rin * 2 + (0 ^ swz)] = u0;
    dst[base + rin * 2 + (1 ^ swz)] = u1;
}

// ---------------------------------------------------------------------------
// Kernel 2: row norms (double accumulate, one fp32 round) — identical to R1.
// ---------------------------------------------------------------------------
__global__ void norms_kernel(const float* __restrict__ X, const float* __restrict__ P) {
    int row = blockIdx.x;
    const float* src = (row < NR) ? (X + (size_t)row * D_FIX)
                                  : (P + (size_t)(row - NR) * D_FIX);
    int t = threadIdx.x;
    double s = 0.0;
#pragma unroll
    for (int i = 0; i < 4; ++i) { float v = src[t + i * 128]; s += (double)v * (double)v; }
#pragma unroll
    for (int o = 16; o > 0; o >>= 1) s += __shfl_down_sync(0xffffffffu, s, o);
    __shared__ double sh[4];
    if ((t & 31) == 0) sh[t >> 5] = s;
    __syncthreads();
    if (t == 0) {
        float r = (float)(sh[0] + sh[1] + sh[2] + sh[3]);
        if (row < NR) g_xnorm[row] = r; else g_pnorm[row - NR] = r;
    }
}

// ---------------------------------------------------------------------------
// Kernel 3: f16 HMMA (f16 accum) GEMM 128x128 + per-8col-group min epilogue.
// 8 warps (2m x 4n), 4-stage cp.async pipeline, k32 chunks — R8 schedule.
// ---------------------------------------------------------------------------
__device__ __forceinline__ void issue_stage(uint32_t sbase, int s, int tid,
                                            const uint4* aSrc, const uint4* bSrc) {
    uint32_t dst = sbase + (uint32_t)(s & 3) * 16384;
#pragma unroll
    for (int i = 0; i < 4; i++) {
        int u = tid + i * 256;
        const uint4* src = (u < 512) ? (aSrc + (size_t)s * 512 + u)
                                     : (bSrc + (size_t)s * 512 + (u - 512));
        cp16(dst + u * 16, src);
    }
}

__global__ __launch_bounds__(256, 2) void gemm_gmin_kernel() {
    extern __shared__ char smem[];
    uint32_t sb = smem_u32(smem);
    float* sAn = (float*)(smem + SMEM_STAGES);
    float* sPn = (float*)(smem + SMEM_STAGES + 512);

    const int tid = threadIdx.x;
    const int colblk = blockIdx.x & (CBLK - 1);
    const int rowblk = blockIdx.x >> 6;
    const int wid = tid >> 5, lane = tid & 31;
    const int wm = wid >> 2, wn = wid & 3;

    if (tid < 128) {
        sAn[tid] = g_xnorm[rowblk * CTA_M + tid];
        sPn[tid] = g_pnorm[colblk * CTA_N + tid];
    }

    const uint4* aSrc = g_A + (size_t)rowblk * NCH16 * TILE_U;
    const uint4* bSrc = g_B + (size_t)colblk * NCH16 * TILE_U;

    issue_stage(sb, 0, tid, aSrc, bSrc); CP_COMMIT();
    issue_stage(sb, 1, tid, aSrc, bSrc); CP_COMMIT();
    issue_stage(sb, 2, tid, aSrc, bSrc); CP_COMMIT();

    uint32_t c[4][4][2];
#pragma unroll
    for (int i = 0; i < 4; i++)
#pragma unroll
        for (int j = 0; j < 4; j++) { c[i][j][0] = 0u; c[i][j][1] = 0u; }

    const int a_r = lane & 15;
    const int a_h = lane >> 4;
    const int b_r = (lane & 7) + ((lane >> 4) << 3);
    const int b_h = (lane >> 3) & 1;

    for (int s = 0; s < NCH32; s++) {
        CP_WAIT2();
        __syncthreads();
        if (s + 3 < NCH32) issue_stage(sb, s + 3, tid, aSrc, bSrc);
        CP_COMMIT();

        uint32_t stg = sb + (uint32_t)(s & 3) * 16384;
#pragma unroll
        for (int t = 0; t < 2; t++) {
            uint32_t sA = stg + t * 4096;
            uint32_t sB = stg + 8192 + t * 4096;

            uint32_t bf[4][2];
#pragma unroll
            for (int jj = 0; jj < 2; jj++) {
                int nrow = wn * 32 + jj * 16 + b_r;
                uint32_t addr = sB + nrow * 32 + ((b_h ^ ((nrow >> 2) & 1)) << 4);
                uint32_t r0, r1, r2, r3;
                LDSM4(r0, r1, r2, r3, addr);
                bf[jj * 2][0] = r0; bf[jj * 2][1] = r1;
                bf[jj * 2 + 1][0] = r2; bf[jj * 2 + 1][1] = r3;
            }
            uint32_t af[4][4];
#pragma unroll
            for (int i = 0; i < 4; i++) {
                int arow = wm * 64 + i * 16 + a_r;
                uint32_t addr = sA + arow * 32 + ((a_h ^ ((arow >> 2) & 1)) << 4);
                LDSM4(af[i][0], af[i][1], af[i][2], af[i][3], addr);
            }
#pragma unroll
            for (int i = 0; i < 4; i++)
#pragma unroll
                for (int j = 0; j < 4; j++)
                    MMAH(c[i][j], af[i], bf[j]);
        }
    }

    // ---- epilogue: per (row, 8-col group) min of approx dist ----
    const int q = lane >> 2;
#pragma unroll
    for (int i = 0; i < 4; i++) {
        int r0 = wm * 64 + i * 16 + q;
        float an0 = sAn[r0], an1 = sAn[r0 + 8];
#pragma unroll
        for (int j = 0; j < 4; j++) {
            int c0 = wn * 32 + j * 8 + (lane & 3) * 2;
            float pn0 = sPn[c0], pn1 = sPn[c0 + 1];
            __half2 h01 = *(__half2*)&c[i][j][0];   // row r0: cols c0, c0+1
            __half2 h23 = *(__half2*)&c[i][j][1];   // row r0+8
            float v00 = __half2float(__low2half(h01));
            float v01 = __half2float(__high2half(h01));
            float v10 = __half2float(__low2half(h23));
            float v11 = __half2float(__high2half(h23));
            float d00 = __fmaf_rn(v00, -2.0f, __fadd_rn(an0, pn0));
            float d01 = __fmaf_rn(v01, -2.0f, __fadd_rn(an0, pn1));
            float d10 = __fmaf_rn(v10, -2.0f, __fadd_rn(an1, pn0));
            float d11 = __fmaf_rn(v11, -2.0f, __fadd_rn(an1, pn1));
            float m0 = fminf(d00, d01);
            float m1 = fminf(d10, d11);
#pragma unroll
            for (int o = 1; o <= 2; o <<= 1) {
                m0 = fminf(m0, __shfl_xor_sync(0xffffffffu, m0, o));
                m1 = fminf(m1, __shfl_xor_sync(0xffffffffu, m1, o));
            }
            if ((lane & 3) == 0) {
                size_t gidx = (size_t)(colblk * 16 + wn * 4 + j) * NR
                            + rowblk * CTA_M + wm * 64 + i * 16;
                g_gmin[gidx + q] = m0;
                g_gmin[gidx + q + 8] = m1;
            }
        }
    }
}

// ---------------------------------------------------------------------------
// Kernel 4a: per-row min over 1024 group-mins (parallel, coalesced).
// ---------------------------------------------------------------------------
__global__ void rowmin_kernel() {
    int tid = threadIdx.x;
    int r = blockIdx.x * 64 + (tid & 63);
    int gl = tid >> 6;
    const float* col = g_gmin + (size_t)gl * 256 * NR + r;
    float mn = 3.402823466e38f;
    for (int g = 0; g < 256; g += 4) {
        float v0 = col[(size_t)(g + 0) * NR];
        float v1 = col[(size_t)(g + 1) * NR];
        float v2 = col[(size_t)(g + 2) * NR];
        float v3 = col[(size_t)(g + 3) * NR];
        mn = fminf(mn, fminf(fminf(v0, v1), fminf(v2, v3)));
    }
    __shared__ float sm[4][64];
    sm[gl][tid & 63] = mn;
    __syncthreads();
    if (tid < 64) {
        float m = fminf(fminf(sm[0][tid], sm[1][tid]), fminf(sm[2][tid], sm[3][tid]));
        int row = blockIdx.x * 64 + tid;
        g_rowthr[row] = m + MARGIN;
        g_bestkey[row] = 0xFFFFFFFFFFFFFFFFull;
    }
}

// ---------------------------------------------------------------------------
// Kernel 4b: flag groups within margin -> worklist.
// ---------------------------------------------------------------------------
__global__ void flag_kernel() {
    int tid = threadIdx.x;
    int r = blockIdx.x * 64 + (tid & 63);
    int gl = tid >> 6;
    float thr = g_rowthr[r];
    const float* col = g_gmin + (size_t)gl * 256 * NR + r;
    for (int g = 0; g < 256; g += 4) {
        float v0 = col[(size_t)(g + 0) * NR];
        float v1 = col[(size_t)(g + 1) * NR];
        float v2 = col[(size_t)(g + 2) * NR];
        float v3 = col[(size_t)(g + 3) * NR];
#pragma unroll
        for (int o = 0; o < 4; o++) {
            float v = (o == 0) ? v0 : (o == 1) ? v1 : (o == 2) ? v2 : v3;
            if (v <= thr) {
                unsigned int idx = atomicAdd(&g_wcount, 1u);
                if (idx < WCAP)
                    g_wlist[idx] = (unsigned)(r * NGRP + gl * 256 + g + o);
            }
        }
    }
}

// ---------------------------------------------------------------------------
// Kernel 5: exact rescore of flagged groups — identical numerics to R1/R5.
// ---------------------------------------------------------------------------
__global__ void rescore_kernel(const float* __restrict__ X, const float* __restrict__ P) {
    unsigned int count = g_wcount;
    if (count > WCAP) count = WCAP;
    for (unsigned int e = blockIdx.x * 256 + threadIdx.x; e < count;
         e += gridDim.x * 256) {
        unsigned int w = g_wlist[e];
        int row = (int)(w >> 10);
        int grp = (int)(w & (NGRP - 1));
        int k0 = grp * 8;
        const float4* x4 = (const float4*)(X + (size_t)row * D_FIX);
        const float4* p4 = (const float4*)(P + (size_t)k0 * D_FIX);
        float acc[8];
#pragma unroll
        for (int c = 0; c < 8; c++) acc[c] = 0.0f;
        for (int d = 0; d < D_FIX / 4; d++) {
            float4 xv = x4[d];
#pragma unroll
            for (int c = 0; c < 8; c++) {
                float4 pv = p4[(size_t)c * (D_FIX / 4) + d];
                acc[c] = __fmaf_rn(xv.x, pv.x, acc[c]);
                acc[c] = __fmaf_rn(xv.y, pv.y, acc[c]);
                acc[c] = __fmaf_rn(xv.z, pv.z, acc[c]);
                acc[c] = __fmaf_rn(xv.w, pv.w, acc[c]);
            }
        }
        float an = g_xnorm[row];
        unsigned long long best = 0xFFFFFFFFFFFFFFFFull;
#pragma unroll
        for (int c = 0; c < 8; c++) {
            float t = __fadd_rn(an, g_pnorm[k0 + c]);
            float d = __fadd_rn(t, __fmul_rn(-2.0f, acc[c]));
            unsigned long long key =
                ((unsigned long long)__float_as_uint(d) << 32) | (unsigned)(k0 + c);
            if (key < best) best = key;
        }
        atomicMin(&g_bestkey[row], best);
    }
}

// ---------------------------------------------------------------------------
// Kernel 6: gather + exact straight-through output + per-row loss partials.
// ---------------------------------------------------------------------------
__global__ void gather_loss_kernel(const float* __restrict__ X,
                                   const float* __restrict__ P,
                                   float* __restrict__ out) {
    int row = blockIdx.x;
    int t = threadIdx.x;
    int c = (int)(unsigned)(g_bestkey[row] & 0xFFFFFFFFull);
    const float* x = X + (size_t)row * D_FIX;
    const float* q = P + (size_t)c * D_FIX;
    float* o = out + (size_t)row * D_FIX;
    double s = 0.0;
#pragma unroll
    for (int i = 0; i < 4; i++) {
        int d = t + i * 128;
        float xv = x[d], qv = q[d];
        float diff = __fsub_rn(qv, xv);
        o[d] = __fadd_rn(xv, diff);
        s += (double)diff * (double)diff;
    }
#pragma unroll
    for (int o2 = 16; o2 > 0; o2 >>= 1) s += __shfl_down_sync(0xffffffffu, s, o2);
    __shared__ double sh[4];
    if ((t & 31) == 0) sh[t >> 5] = s;
    __syncthreads();
    if (t == 0) g_losspart[row] = sh[0] + sh[1] + sh[2] + sh[3];
}

// ---------------------------------------------------------------------------
// Kernel 7a: partial loss sums. 7b: final loss.
// ---------------------------------------------------------------------------
__global__ void losssum_kernel() {
    __shared__ double sh[256];
    int t = threadIdx.x;
    sh[t] = g_losspart[blockIdx.x * 256 + t];
    __syncthreads();
    for (int o = 128; o > 0; o >>= 1) {
        if (t < o) sh[t] += sh[t + o];
        __syncthreads();
    }
    if (t == 0) g_losspart2[blockIdx.x] = sh[0];
}

__global__ void finalize_kernel(float* __restrict__ out,
                                long long tail_start, long long out_sz) {
    __shared__ double sh[128];
    int t = threadIdx.x;
    sh[t] = g_losspart2[t];
    __syncthreads();
    for (int o = 64; o > 0; o >>= 1) {
        if (t < o) sh[t] += sh[t + o];
        __syncthreads();
    }
    if (t == 0) {
        double mean = sh[0] / ((double)NR * (double)D_FIX);
        float m = (float)mean;
        float v = __fadd_rn(__fmul_rn(m, 0.25f), m);
        for (long long i = tail_start; i < out_sz; ++i) out[i] = v;
    }
}

// ---------------------------------------------------------------------------
extern "C" void kernel_launch(void* const* d_in, const int* in_sizes, int n_in,
                              void* d_out, int out_size) {
    const float* X = (const float*)d_in[0];
    const float* P = (const float*)d_in[1];
    float* out = (float*)d_out;

    cudaFuncSetAttribute(gemm_gmin_kernel,
                         cudaFuncAttributeMaxDynamicSharedMemorySize, SMEM_TOTAL);

    prep_kernel<<<(NR * NCH16 + KP * NCH16) / 256, 256>>>(X, P);
    norms_kernel<<<NR + KP, 128>>>(X, P);
    gemm_gmin_kernel<<<RBLK * CBLK, 256, SMEM_TOTAL>>>();
    rowmin_kernel<<<NR / 64, 256>>>();
    flag_kernel<<<NR / 64, 256>>>();
    rescore_kernel<<<1024, 256>>>(X, P);
    gather_loss_kernel<<<NR, 128>>>(X, P, out);
    losssum_kernel<<<128, 256>>>();
    finalize_kernel<<<1, 128>>>(out, (long long)NR * D_FIX, (long long)out_size);
}

// round 11
// speedup vs baseline: 1.7241x; 1.4836x over previous
#include <cuda_runtime.h>
#include <cuda_bf16.h>
#include <cstdint>

#define D_FIX 512
#define NR 32768
#define KP 8192
#define CTA_M 128
#define CTA_N 128
#define NCH16 32               // k tiles of 16
#define NCH32 16               // pipeline chunks of k32
#define RBLK (NR/CTA_M)        // 256
#define CBLK (KP/CTA_N)        // 64
#define NGRP (KP/8)            // 1024 groups of 8 cols
#define TILE_U 256             // 16B units per 4KB k16 tile
#define SMEM_STAGES (4*16384)  // 4 stages x 16KB (A 8KB + B 8KB)
#define SMEM_TOTAL  (SMEM_STAGES + 512 + 512)
#define MARGIN 1e-3f
#define WCAP (1u<<22)

// ---- device-global scratch (allocations forbidden) ----
__device__ uint4  g_A[(size_t)RBLK * NCH16 * TILE_U];    // 32MB (bf16 hi split)
__device__ uint4  g_B[(size_t)CBLK * NCH16 * TILE_U];    // 8MB
__device__ float  g_xnorm[NR];
__device__ float  g_pnorm[KP];
__device__ float  g_gmin[(size_t)NGRP * NR];             // 128MB [group][row]
__device__ unsigned int g_rowub[NR];                     // approx row-min (bits)
__device__ unsigned long long g_bestkey[NR];
__device__ unsigned int g_wcount;
__device__ unsigned int g_wlist[WCAP];
__device__ double g_losspart[NR];
__device__ double g_losspart2[128];

// ---------------- PTX helpers (baseline sm_80-class only) ----------------
__device__ __forceinline__ uint32_t smem_u32(const void* p) {
    uint32_t a;
    asm("{ .reg .u64 t; cvta.to.shared.u64 t, %1; cvt.u32.u64 %0, t; }" : "=r"(a) : "l"(p));
    return a;
}
__device__ __forceinline__ void cp16(uint32_t dst, const void* src) {
    asm volatile("cp.async.cg.shared.global [%0], [%1], 16;" :: "r"(dst), "l"(src));
}
#define CP_COMMIT() asm volatile("cp.async.commit_group;")
#define CP_WAIT2()  asm volatile("cp.async.wait_group 2;")

#define LDSM4(r0, r1, r2, r3, addr) \
    asm volatile("ldmatrix.sync.aligned.m8n8.x4.shared.b16 {%0,%1,%2,%3}, [%4];" \
        : "=r"(r0), "=r"(r1), "=r"(r2), "=r"(r3) : "r"(addr))

#define MMA(c, a, b) \
    asm volatile("mma.sync.aligned.m16n8k16.row.col.f32.bf16.bf16.f32 " \
        "{%0,%1,%2,%3}, {%4,%5,%6,%7}, {%8,%9}, {%0,%1,%2,%3};" \
        : "+f"((c)[0]), "+f"((c)[1]), "+f"((c)[2]), "+f"((c)[3]) \
        : "r"((a)[0]), "r"((a)[1]), "r"((a)[2]), "r"((a)[3]), \
          "r"((b)[0]), "r"((b)[1]))

// ---------------------------------------------------------------------------
// Kernel 1: hi-bf16 convert, pre-swizzled tiled layout (validated R5-R8).
// unit(r, half) = r*2 + (half ^ ((r>>2)&1))  — conflict-free for ldmatrix.
// ---------------------------------------------------------------------------
__global__ void prep_kernel(const float* __restrict__ X, const float* __restrict__ P) {
    int gid = blockIdx.x * 256 + threadIdx.x;
    const int xcnt = NR * NCH16;
    bool isX = gid < xcnt;
    int g = isX ? gid : gid - xcnt;
    int row, chunk;
    if (isX) { row = g & (NR - 1); chunk = g >> 15; }
    else     { row = g & (KP - 1); chunk = g >> 13; }
    const float4* src = (const float4*)((isX ? X : P) + (size_t)row * D_FIX + chunk * 16);

    unsigned short hv[16];
#pragma unroll
    for (int i = 0; i < 4; i++) {
        float4 v = src[i];
        hv[i * 4 + 0] = __bfloat16_as_ushort(__float2bfloat16_rn(v.x));
        hv[i * 4 + 1] = __bfloat16_as_ushort(__float2bfloat16_rn(v.y));
        hv[i * 4 + 2] = __bfloat16_as_ushort(__float2bfloat16_rn(v.z));
        hv[i * 4 + 3] = __bfloat16_as_ushort(__float2bfloat16_rn(v.w));
    }
    int rin = row & 127;
    int blk = row >> 7;
    size_t base = (size_t)(blk * NCH16 + chunk) * TILE_U;
    int swz = (rin >> 2) & 1;
    uint4* dst = isX ? g_A : g_B;
    uint4 u0, u1;
    u0.x = hv[0]  | ((uint32_t)hv[1]  << 16);
    u0.y = hv[2]  | ((uint32_t)hv[3]  << 16);
    u0.z = hv[4]  | ((uint32_t)hv[5]  << 16);
    u0.w = hv[6]  | ((uint32_t)hv[7]  << 16);
    u1.x = hv[8]  | ((uint32_t)hv[9]  << 16);
    u1.y = hv[10] | ((uint32_t)hv[11] << 16);
    u1.z = hv[12] | ((uint32_t)hv[13] << 16);
    u1.w = hv[14] | ((uint32_t)hv[15] << 16);
    dst[base + rin * 2 + (0 ^ swz)] = u0;
    dst[base + rin * 2 + (1 ^ swz)] = u1;
}

// ---------------------------------------------------------------------------
// Kernel 2: row norms (double accumulate, one fp32 round — identical to R1)
// + init of rowub/bestkey/wcount (runs before the GEMM).
// ---------------------------------------------------------------------------
__global__ void norms_kernel(const float* __restrict__ X, const float* __restrict__ P) {
    int row = blockIdx.x;
    const float* src = (row < NR) ? (X + (size_t)row * D_FIX)
                                  : (P + (size_t)(row - NR) * D_FIX);
    int t = threadIdx.x;
    double s = 0.0;
#pragma unroll
    for (int i = 0; i < 4; ++i) { float v = src[t + i * 128]; s += (double)v * (double)v; }
#pragma unroll
    for (int o = 16; o > 0; o >>= 1) s += __shfl_down_sync(0xffffffffu, s, o);
    __shared__ double sh[4];
    if ((t & 31) == 0) sh[t >> 5] = s;
    __syncthreads();
    if (t == 0) {
        float r = (float)(sh[0] + sh[1] + sh[2] + sh[3]);
        if (row < NR) {
            g_xnorm[row] = r;
            g_rowub[row] = 0x7F800000u;               // +inf
            g_bestkey[row] = 0xFFFFFFFFFFFFFFFFull;
            if (row == 0) g_wcount = 0;
        } else {
            g_pnorm[row - NR] = r;
        }
    }
}

// ---------------------------------------------------------------------------
// Kernel 3: HMMA bf16 (f32 accum) GEMM 128x128 + per-8col-group min epilogue
// + per-row atomicMin of approx dist (replaces the rowmin kernel).
// 8 warps (2m x 4n), 4-stage cp.async pipeline, k32 chunks — R8 schedule.
// ---------------------------------------------------------------------------
__device__ __forceinline__ void issue_stage(uint32_t sbase, int s, int tid,
                                            const uint4* aSrc, const uint4* bSrc) {
    uint32_t dst = sbase + (uint32_t)(s & 3) * 16384;
#pragma unroll
    for (int i = 0; i < 4; i++) {
        int u = tid + i * 256;
        const uint4* src = (u < 512) ? (aSrc + (size_t)s * 512 + u)
                                     : (bSrc + (size_t)s * 512 + (u - 512));
        cp16(dst + u * 16, src);
    }
}

__global__ __launch_bounds__(256, 2) void gemm_gmin_kernel() {
    extern __shared__ char smem[];
    uint32_t sb = smem_u32(smem);
    float* sAn = (float*)(smem + SMEM_STAGES);
    float* sPn = (float*)(smem + SMEM_STAGES + 512);

    const int tid = threadIdx.x;
    const int colblk = blockIdx.x & (CBLK - 1);
    const int rowblk = blockIdx.x >> 6;
    const int wid = tid >> 5, lane = tid & 31;
    const int wm = wid >> 2, wn = wid & 3;

    if (tid < 128) {
        sAn[tid] = g_xnorm[rowblk * CTA_M + tid];
        sPn[tid] = g_pnorm[colblk * CTA_N + tid];
    }

    const uint4* aSrc = g_A + (size_t)rowblk * NCH16 * TILE_U;
    const uint4* bSrc = g_B + (size_t)colblk * NCH16 * TILE_U;

    issue_stage(sb, 0, tid, aSrc, bSrc); CP_COMMIT();
    issue_stage(sb, 1, tid, aSrc, bSrc); CP_COMMIT();
    issue_stage(sb, 2, tid, aSrc, bSrc); CP_COMMIT();

    float c[4][4][4];
#pragma unroll
    for (int i = 0; i < 4; i++)
#pragma unroll
        for (int j = 0; j < 4; j++)
#pragma unroll
            for (int v = 0; v < 4; v++) c[i][j][v] = 0.0f;

    const int a_r = lane & 15;
    const int a_h = lane >> 4;
    const int b_r = (lane & 7) + ((lane >> 4) << 3);
    const int b_h = (lane >> 3) & 1;

    for (int s = 0; s < NCH32; s++) {
        CP_WAIT2();
        __syncthreads();
        if (s + 3 < NCH32) issue_stage(sb, s + 3, tid, aSrc, bSrc);
        CP_COMMIT();

        uint32_t stg = sb + (uint32_t)(s & 3) * 16384;
#pragma unroll
        for (int t = 0; t < 2; t++) {
            uint32_t sA = stg + t * 4096;
            uint32_t sB = stg + 8192 + t * 4096;

            uint32_t bf[4][2];
#pragma unroll
            for (int jj = 0; jj < 2; jj++) {
                int nrow = wn * 32 + jj * 16 + b_r;
                uint32_t addr = sB + nrow * 32 + ((b_h ^ ((nrow >> 2) & 1)) << 4);
                uint32_t r0, r1, r2, r3;
                LDSM4(r0, r1, r2, r3, addr);
                bf[jj * 2][0] = r0; bf[jj * 2][1] = r1;
                bf[jj * 2 + 1][0] = r2; bf[jj * 2 + 1][1] = r3;
            }
            uint32_t af[4][4];
#pragma unroll
            for (int i = 0; i < 4; i++) {
                int arow = wm * 64 + i * 16 + a_r;
                uint32_t addr = sA + arow * 32 + ((a_h ^ ((arow >> 2) & 1)) << 4);
                LDSM4(af[i][0], af[i][1], af[i][2], af[i][3], addr);
            }
#pragma unroll
            for (int i = 0; i < 4; i++)
#pragma unroll
                for (int j = 0; j < 4; j++)
                    MMA(c[i][j], af[i], bf[j]);
        }
    }

    // ---- epilogue: group mins + per-row running min -> atomicMin ----
    const int q = lane >> 2;
    float rub0[4], rub1[4];
#pragma unroll
    for (int i = 0; i < 4; i++) { rub0[i] = 3.402823466e38f; rub1[i] = 3.402823466e38f; }

#pragma unroll
    for (int i = 0; i < 4; i++) {
        int r0 = wm * 64 + i * 16 + q;
        float an0 = sAn[r0], an1 = sAn[r0 + 8];
#pragma unroll
        for (int j = 0; j < 4; j++) {
            int c0 = wn * 32 + j * 8 + (lane & 3) * 2;
            float pn0 = sPn[c0], pn1 = sPn[c0 + 1];
            float d00 = __fadd_rn(__fadd_rn(an0, pn0), __fmul_rn(-2.0f, c[i][j][0]));
            float d01 = __fadd_rn(__fadd_rn(an0, pn1), __fmul_rn(-2.0f, c[i][j][1]));
            float d10 = __fadd_rn(__fadd_rn(an1, pn0), __fmul_rn(-2.0f, c[i][j][2]));
            float d11 = __fadd_rn(__fadd_rn(an1, pn1), __fmul_rn(-2.0f, c[i][j][3]));
            float m0 = fminf(d00, d01);
            float m1 = fminf(d10, d11);
#pragma unroll
            for (int o = 1; o <= 2; o <<= 1) {
                m0 = fminf(m0, __shfl_xor_sync(0xffffffffu, m0, o));
                m1 = fminf(m1, __shfl_xor_sync(0xffffffffu, m1, o));
            }
            rub0[i] = fminf(rub0[i], m0);
            rub1[i] = fminf(rub1[i], m1);
            if ((lane & 3) == 0) {
                size_t gidx = (size_t)(colblk * 16 + wn * 4 + j) * NR
                            + rowblk * CTA_M + wm * 64 + i * 16;
                g_gmin[gidx + q] = m0;
                g_gmin[gidx + q + 8] = m1;
            }
        }
    }
    if ((lane & 3) == 0) {
#pragma unroll
        for (int i = 0; i < 4; i++) {
            int r0 = rowblk * CTA_M + wm * 64 + i * 16 + q;
            atomicMin(&g_rowub[r0], __float_as_uint(rub0[i]));
            atomicMin(&g_rowub[r0 + 8], __float_as_uint(rub1[i]));
        }
    }
}

// ---------------------------------------------------------------------------
// Kernel 4: flag groups within margin -> worklist.
// ---------------------------------------------------------------------------
__global__ void flag_kernel() {
    int tid = threadIdx.x;
    int r = blockIdx.x * 64 + (tid & 63);
    int gl = tid >> 6;
    float thr = __uint_as_float(g_rowub[r]) + MARGIN;
    const float* col = g_gmin + (size_t)gl * 256 * NR + r;
    for (int g = 0; g < 256; g += 4) {
        float v0 = col[(size_t)(g + 0) * NR];
        float v1 = col[(size_t)(g + 1) * NR];
        float v2 = col[(size_t)(g + 2) * NR];
        float v3 = col[(size_t)(g + 3) * NR];
#pragma unroll
        for (int o = 0; o < 4; o++) {
            float v = (o == 0) ? v0 : (o == 1) ? v1 : (o == 2) ? v2 : v3;
            if (v <= thr) {
                unsigned int idx = atomicAdd(&g_wcount, 1u);
                if (idx < WCAP)
                    g_wlist[idx] = (unsigned)(r * NGRP + gl * 256 + g + o);
            }
        }
    }
}

// ---------------------------------------------------------------------------
// Kernel 5: exact rescore of flagged groups — identical numerics to R1/R5.
// ---------------------------------------------------------------------------
__global__ void rescore_kernel(const float* __restrict__ X, const float* __restrict__ P) {
    unsigned int count = g_wcount;
    if (count > WCAP) count = WCAP;
    for (unsigned int e = blockIdx.x * 256 + threadIdx.x; e < count;
         e += gridDim.x * 256) {
        unsigned int w = g_wlist[e];
        int row = (int)(w >> 10);
        int grp = (int)(w & (NGRP - 1));
        int k0 = grp * 8;
        const float4* x4 = (const float4*)(X + (size_t)row * D_FIX);
        const float4* p4 = (const float4*)(P + (size_t)k0 * D_FIX);
        float acc[8];
#pragma unroll
        for (int c = 0; c < 8; c++) acc[c] = 0.0f;
        for (int d = 0; d < D_FIX / 4; d++) {
            float4 xv = x4[d];
#pragma unroll
            for (int c = 0; c < 8; c++) {
                float4 pv = p4[(size_t)c * (D_FIX / 4) + d];
                acc[c] = __fmaf_rn(xv.x, pv.x, acc[c]);
                acc[c] = __fmaf_rn(xv.y, pv.y, acc[c]);
                acc[c] = __fmaf_rn(xv.z, pv.z, acc[c]);
                acc[c] = __fmaf_rn(xv.w, pv.w, acc[c]);
            }
        }
        float an = g_xnorm[row];
        unsigned long long best = 0xFFFFFFFFFFFFFFFFull;
#pragma unroll
        for (int c = 0; c < 8; c++) {
            float t = __fadd_rn(an, g_pnorm[k0 + c]);
            float d = __fadd_rn(t, __fmul_rn(-2.0f, acc[c]));
            unsigned long long key =
                ((unsigned long long)__float_as_uint(d) << 32) | (unsigned)(k0 + c);
            if (key < best) best = key;
        }
        atomicMin(&g_bestkey[row], best);
    }
}

// ---------------------------------------------------------------------------
// Kernel 6: gather + exact straight-through output + per-row loss partials.
// ---------------------------------------------------------------------------
__global__ void gather_loss_kernel(const float* __restrict__ X,
                                   const float* __restrict__ P,
                                   float* __restrict__ out) {
    int row = blockIdx.x;
    int t = threadIdx.x;
    int c = (int)(unsigned)(g_bestkey[row] & 0xFFFFFFFFull);
    const float* x = X + (size_t)row * D_FIX;
    const float* q = P + (size_t)c * D_FIX;
    float* o = out + (size_t)row * D_FIX;
    double s = 0.0;
#pragma unroll
    for (int i = 0; i < 4; i++) {
        int d = t + i * 128;
        float xv = x[d], qv = q[d];
        float diff = __fsub_rn(qv, xv);
        o[d] = __fadd_rn(xv, diff);
        s += (double)diff * (double)diff;
    }
#pragma unroll
    for (int o2 = 16; o2 > 0; o2 >>= 1) s += __shfl_down_sync(0xffffffffu, s, o2);
    __shared__ double sh[4];
    if ((t & 31) == 0) sh[t >> 5] = s;
    __syncthreads();
    if (t == 0) g_losspart[row] = sh[0] + sh[1] + sh[2] + sh[3];
}

// ---------------------------------------------------------------------------
// Kernel 7a: partial loss sums. 7b: final loss = fl(fl(mse*0.25) + mse).
// ---------------------------------------------------------------------------
__global__ void losssum_kernel() {
    __shared__ double sh[256];
    int t = threadIdx.x;
    sh[t] = g_losspart[blockIdx.x * 256 + t];
    __syncthreads();
    for (int o = 128; o > 0; o >>= 1) {
        if (t < o) sh[t] += sh[t + o];
        __syncthreads();
    }
    if (t == 0) g_losspart2[blockIdx.x] = sh[0];
}

__global__ void finalize_kernel(float* __restrict__ out,
                                long long tail_start, long long out_sz) {
    __shared__ double sh[128];
    int t = threadIdx.x;
    sh[t] = g_losspart2[t];
    __syncthreads();
    for (int o = 64; o > 0; o >>= 1) {
        if (t < o) sh[t] += sh[t + o];
        __syncthreads();
    }
    if (t == 0) {
        double mean = sh[0] / ((double)NR * (double)D_FIX);
        float m = (float)mean;
        float v = __fadd_rn(__fmul_rn(m, 0.25f), m);
        for (long long i = tail_start; i < out_sz; ++i) out[i] = v;
    }
}

// ---------------------------------------------------------------------------
extern "C" void kernel_launch(void* const* d_in, const int* in_sizes, int n_in,
                              void* d_out, int out_size) {
    const float* X = (const float*)d_in[0];
    const float* P = (const float*)d_in[1];
    float* out = (float*)d_out;

    cudaFuncSetAttribute(gemm_gmin_kernel,
                         cudaFuncAttributeMaxDynamicSharedMemorySize, SMEM_TOTAL);

    norms_kernel<<<NR + KP, 128>>>(X, P);    // also inits rowub/bestkey/wcount
    prep_kernel<<<(NR * NCH16 + KP * NCH16) / 256, 256>>>(X, P);
    gemm_gmin_kernel<<<RBLK * CBLK, 256, SMEM_TOTAL>>>();
    flag_kernel<<<NR / 64, 256>>>();
    rescore_kernel<<<1024, 256>>>(X, P);
    gather_loss_kernel<<<NR, 128>>>(X, P, out);
    losssum_kernel<<<128, 256>>>();
    finalize_kernel<<<1, 128>>>(out, (long long)NR * D_FIX, (long long)out_size);
}

// round 12
// speedup vs baseline: 1.7658x; 1.0242x over previous
#include <cuda_runtime.h>
#include <cuda_bf16.h>
#include <cstdint>

#define D_FIX 512
#define NR 32768
#define KP 8192
#define CTA_M 128
#define CTA_N 128
#define NCH16 32               // k tiles of 16
#define NCH32 16               // pipeline chunks of k32
#define RBLK (NR/CTA_M)        // 256
#define CBLK (KP/CTA_N)        // 64
#define NGRP (KP/8)            // 1024 groups of 8 cols
#define TILE_U 256             // 16B units per 4KB k16 tile
#define SMEM_STAGES (4*16384)  // 4 stages x 16KB (A 8KB + B 8KB)
#define SMEM_TOTAL  (SMEM_STAGES + 512 + 512)
#define MARGIN 1e-3f
#define WCAP (1u<<22)

// ---- device-global scratch (allocations forbidden) ----
__device__ uint4  g_A[(size_t)RBLK * NCH16 * TILE_U];    // 32MB (bf16 hi)
__device__ uint4  g_B[(size_t)CBLK * NCH16 * TILE_U];    // 8MB
__device__ float  g_xnorm[NR];
__device__ float  g_pnorm[KP];
__device__ float  g_gmin[(size_t)NGRP * NR];             // 128MB [group][row]
__device__ unsigned int g_rowub[NR];                     // approx row-min (bits)
__device__ unsigned long long g_bestkey[NR];
__device__ unsigned int g_wcount;
__device__ unsigned int g_wlist[WCAP];
__device__ double g_losspart[NR];
__device__ double g_losspart2[128];

// ---------------- PTX helpers (baseline sm_80-class only) ----------------
__device__ __forceinline__ uint32_t smem_u32(const void* p) {
    uint32_t a;
    asm("{ .reg .u64 t; cvta.to.shared.u64 t, %1; cvt.u32.u64 %0, t; }" : "=r"(a) : "l"(p));
    return a;
}
__device__ __forceinline__ void cp16(uint32_t dst, const void* src) {
    asm volatile("cp.async.cg.shared.global [%0], [%1], 16;" :: "r"(dst), "l"(src));
}
#define CP_COMMIT() asm volatile("cp.async.commit_group;")
#define CP_WAIT2()  asm volatile("cp.async.wait_group 2;")

#define LDSM4(r0, r1, r2, r3, addr) \
    asm volatile("ldmatrix.sync.aligned.m8n8.x4.shared.b16 {%0,%1,%2,%3}, [%4];" \
        : "=r"(r0), "=r"(r1), "=r"(r2), "=r"(r3) : "r"(addr))

#define MMA(c, a, b) \
    asm volatile("mma.sync.aligned.m16n8k16.row.col.f32.bf16.bf16.f32 " \
        "{%0,%1,%2,%3}, {%4,%5,%6,%7}, {%8,%9}, {%0,%1,%2,%3};" \
        : "+f"((c)[0]), "+f"((c)[1]), "+f"((c)[2]), "+f"((c)[3]) \
        : "r"((a)[0]), "r"((a)[1]), "r"((a)[2]), "r"((a)[3]), \
          "r"((b)[0]), "r"((b)[1]))

// ---------------------------------------------------------------------------
// Kernel 1: hi-bf16 convert, pre-swizzled tiled layout (validated R5-R11).
// unit(r, half) = r*2 + (half ^ ((r>>2)&1))  — conflict-free for ldmatrix.
// ---------------------------------------------------------------------------
__global__ void prep_kernel(const float* __restrict__ X, const float* __restrict__ P) {
    int gid = blockIdx.x * 256 + threadIdx.x;
    const int xcnt = NR * NCH16;
    bool isX = gid < xcnt;
    int g = isX ? gid : gid - xcnt;
    int row, chunk;
    if (isX) { row = g & (NR - 1); chunk = g >> 15; }
    else     { row = g & (KP - 1); chunk = g >> 13; }
    const float4* src = (const float4*)((isX ? X : P) + (size_t)row * D_FIX + chunk * 16);

    unsigned short hv[16];
#pragma unroll
    for (int i = 0; i < 4; i++) {
        float4 v = src[i];
        hv[i * 4 + 0] = __bfloat16_as_ushort(__float2bfloat16_rn(v.x));
        hv[i * 4 + 1] = __bfloat16_as_ushort(__float2bfloat16_rn(v.y));
        hv[i * 4 + 2] = __bfloat16_as_ushort(__float2bfloat16_rn(v.z));
        hv[i * 4 + 3] = __bfloat16_as_ushort(__float2bfloat16_rn(v.w));
    }
    int rin = row & 127;
    int blk = row >> 7;
    size_t base = (size_t)(blk * NCH16 + chunk) * TILE_U;
    int swz = (rin >> 2) & 1;
    uint4* dst = isX ? g_A : g_B;
    uint4 u0, u1;
    u0.x = hv[0]  | ((uint32_t)hv[1]  << 16);
    u0.y = hv[2]  | ((uint32_t)hv[3]  << 16);
    u0.z = hv[4]  | ((uint32_t)hv[5]  << 16);
    u0.w = hv[6]  | ((uint32_t)hv[7]  << 16);
    u1.x = hv[8]  | ((uint32_t)hv[9]  << 16);
    u1.y = hv[10] | ((uint32_t)hv[11] << 16);
    u1.z = hv[12] | ((uint32_t)hv[13] << 16);
    u1.w = hv[14] | ((uint32_t)hv[15] << 16);
    dst[base + rin * 2 + (0 ^ swz)] = u0;
    dst[base + rin * 2 + (1 ^ swz)] = u1;
}

// ---------------------------------------------------------------------------
// Kernel 2: row norms (double accumulate, one fp32 round — identical to R1)
// + init of rowub/bestkey/wcount.
// ---------------------------------------------------------------------------
__global__ void norms_kernel(const float* __restrict__ X, const float* __restrict__ P) {
    int row = blockIdx.x;
    const float* src = (row < NR) ? (X + (size_t)row * D_FIX)
                                  : (P + (size_t)(row - NR) * D_FIX);
    int t = threadIdx.x;
    double s = 0.0;
#pragma unroll
    for (int i = 0; i < 4; ++i) { float v = src[t + i * 128]; s += (double)v * (double)v; }
#pragma unroll
    for (int o = 16; o > 0; o >>= 1) s += __shfl_down_sync(0xffffffffu, s, o);
    __shared__ double sh[4];
    if ((t & 31) == 0) sh[t >> 5] = s;
    __syncthreads();
    if (t == 0) {
        float r = (float)(sh[0] + sh[1] + sh[2] + sh[3]);
        if (row < NR) {
            g_xnorm[row] = r;
            g_rowub[row] = 0x7F800000u;               // +inf
            g_bestkey[row] = 0xFFFFFFFFFFFFFFFFull;
            if (row == 0) g_wcount = 0;
        } else {
            g_pnorm[row - NR] = r;
        }
    }
}

// ---------------------------------------------------------------------------
// Kernel 3: HMMA bf16 (f32 accum) GEMM 128x128 + group-min epilogue +
// per-row atomicMin — byte-identical to R11.
// ---------------------------------------------------------------------------
__device__ __forceinline__ void issue_stage(uint32_t sbase, int s, int tid,
                                            const uint4* aSrc, const uint4* bSrc) {
    uint32_t dst = sbase + (uint32_t)(s & 3) * 16384;
#pragma unroll
    for (int i = 0; i < 4; i++) {
        int u = tid + i * 256;
        const uint4* src = (u < 512) ? (aSrc + (size_t)s * 512 + u)
                                     : (bSrc + (size_t)s * 512 + (u - 512));
        cp16(dst + u * 16, src);
    }
}

__global__ __launch_bounds__(256, 2) void gemm_gmin_kernel() {
    extern __shared__ char smem[];
    uint32_t sb = smem_u32(smem);
    float* sAn = (float*)(smem + SMEM_STAGES);
    float* sPn = (float*)(smem + SMEM_STAGES + 512);

    const int tid = threadIdx.x;
    const int colblk = blockIdx.x & (CBLK - 1);
    const int rowblk = blockIdx.x >> 6;
    const int wid = tid >> 5, lane = tid & 31;
    const int wm = wid >> 2, wn = wid & 3;

    if (tid < 128) {
        sAn[tid] = g_xnorm[rowblk * CTA_M + tid];
        sPn[tid] = g_pnorm[colblk * CTA_N + tid];
    }

    const uint4* aSrc = g_A + (size_t)rowblk * NCH16 * TILE_U;
    const uint4* bSrc = g_B + (size_t)colblk * NCH16 * TILE_U;

    issue_stage(sb, 0, tid, aSrc, bSrc); CP_COMMIT();
    issue_stage(sb, 1, tid, aSrc, bSrc); CP_COMMIT();
    issue_stage(sb, 2, tid, aSrc, bSrc); CP_COMMIT();

    float c[4][4][4];
#pragma unroll
    for (int i = 0; i < 4; i++)
#pragma unroll
        for (int j = 0; j < 4; j++)
#pragma unroll
            for (int v = 0; v < 4; v++) c[i][j][v] = 0.0f;

    const int a_r = lane & 15;
    const int a_h = lane >> 4;
    const int b_r = (lane & 7) + ((lane >> 4) << 3);
    const int b_h = (lane >> 3) & 1;

    for (int s = 0; s < NCH32; s++) {
        CP_WAIT2();
        __syncthreads();
        if (s + 3 < NCH32) issue_stage(sb, s + 3, tid, aSrc, bSrc);
        CP_COMMIT();

        uint32_t stg = sb + (uint32_t)(s & 3) * 16384;
#pragma unroll
        for (int t = 0; t < 2; t++) {
            uint32_t sA = stg + t * 4096;
            uint32_t sB = stg + 8192 + t * 4096;

            uint32_t bf[4][2];
#pragma unroll
            for (int jj = 0; jj < 2; jj++) {
                int nrow = wn * 32 + jj * 16 + b_r;
                uint32_t addr = sB + nrow * 32 + ((b_h ^ ((nrow >> 2) & 1)) << 4);
                uint32_t r0, r1, r2, r3;
                LDSM4(r0, r1, r2, r3, addr);
                bf[jj * 2][0] = r0; bf[jj * 2][1] = r1;
                bf[jj * 2 + 1][0] = r2; bf[jj * 2 + 1][1] = r3;
            }
            uint32_t af[4][4];
#pragma unroll
            for (int i = 0; i < 4; i++) {
                int arow = wm * 64 + i * 16 + a_r;
                uint32_t addr = sA + arow * 32 + ((a_h ^ ((arow >> 2) & 1)) << 4);
                LDSM4(af[i][0], af[i][1], af[i][2], af[i][3], addr);
            }
#pragma unroll
            for (int i = 0; i < 4; i++)
#pragma unroll
                for (int j = 0; j < 4; j++)
                    MMA(c[i][j], af[i], bf[j]);
        }
    }

    // ---- epilogue: group mins + per-row running min -> atomicMin ----
    const int q = lane >> 2;
    float rub0[4], rub1[4];
#pragma unroll
    for (int i = 0; i < 4; i++) { rub0[i] = 3.402823466e38f; rub1[i] = 3.402823466e38f; }

#pragma unroll
    for (int i = 0; i < 4; i++) {
        int r0 = wm * 64 + i * 16 + q;
        float an0 = sAn[r0], an1 = sAn[r0 + 8];
#pragma unroll
        for (int j = 0; j < 4; j++) {
            int c0 = wn * 32 + j * 8 + (lane & 3) * 2;
            float pn0 = sPn[c0], pn1 = sPn[c0 + 1];
            float d00 = __fadd_rn(__fadd_rn(an0, pn0), __fmul_rn(-2.0f, c[i][j][0]));
            float d01 = __fadd_rn(__fadd_rn(an0, pn1), __fmul_rn(-2.0f, c[i][j][1]));
            float d10 = __fadd_rn(__fadd_rn(an1, pn0), __fmul_rn(-2.0f, c[i][j][2]));
            float d11 = __fadd_rn(__fadd_rn(an1, pn1), __fmul_rn(-2.0f, c[i][j][3]));
            float m0 = fminf(d00, d01);
            float m1 = fminf(d10, d11);
#pragma unroll
            for (int o = 1; o <= 2; o <<= 1) {
                m0 = fminf(m0, __shfl_xor_sync(0xffffffffu, m0, o));
                m1 = fminf(m1, __shfl_xor_sync(0xffffffffu, m1, o));
            }
            rub0[i] = fminf(rub0[i], m0);
            rub1[i] = fminf(rub1[i], m1);
            if ((lane & 3) == 0) {
                size_t gidx = (size_t)(colblk * 16 + wn * 4 + j) * NR
                            + rowblk * CTA_M + wm * 64 + i * 16;
                g_gmin[gidx + q] = m0;
                g_gmin[gidx + q + 8] = m1;
            }
        }
    }
    if ((lane & 3) == 0) {
#pragma unroll
        for (int i = 0; i < 4; i++) {
            int r0 = rowblk * CTA_M + wm * 64 + i * 16 + q;
            atomicMin(&g_rowub[r0], __float_as_uint(rub0[i]));
            atomicMin(&g_rowub[r0 + 8], __float_as_uint(rub1[i]));
        }
    }
}

// ---------------------------------------------------------------------------
// Kernel 4: flag groups within margin -> worklist. Ballot-aggregated:
// pure 4-wide loads, one ballot per group slot, zero-hit fast path,
// single leader atomicAdd per warp-batch, popc-prefix scatter.
// ---------------------------------------------------------------------------
__global__ void flag_kernel() {
    int tid = threadIdx.x;
    int lane = tid & 31;
    int r = blockIdx.x * 64 + (tid & 63);
    int gl = tid >> 6;
    float thr = __uint_as_float(g_rowub[r]) + MARGIN;
    const float* col = g_gmin + (size_t)gl * 256 * NR + r;
    unsigned lt_mask = (1u << lane) - 1u;

    for (int g = 0; g < 256; g += 4) {
        float v0 = col[(size_t)(g + 0) * NR];
        float v1 = col[(size_t)(g + 1) * NR];
        float v2 = col[(size_t)(g + 2) * NR];
        float v3 = col[(size_t)(g + 3) * NR];
#pragma unroll
        for (int o = 0; o < 4; o++) {
            float v = (o == 0) ? v0 : (o == 1) ? v1 : (o == 2) ? v2 : v3;
            unsigned mask = __ballot_sync(0xffffffffu, v <= thr);
            if (mask) {
                unsigned base;
                if (lane == (int)(__ffs(mask) - 1))
                    base = atomicAdd(&g_wcount, (unsigned)__popc(mask));
                base = __shfl_sync(0xffffffffu, base, (int)(__ffs(mask) - 1));
                if (v <= thr) {
                    unsigned idx = base + (unsigned)__popc(mask & lt_mask);
                    if (idx < WCAP)
                        g_wlist[idx] = (unsigned)(r * NGRP + gl * 256 + g + o);
                }
            }
        }
    }
}

// ---------------------------------------------------------------------------
// Kernel 5: exact rescore — one thread per (entry, column). Per-column
// sequential fp32 FMA chain d=0..511 in the SAME order as R1/R5-R11;
// dist = fl(fl(an+pn) - 2*dot); u64 key atomicMin (commutative).
// ---------------------------------------------------------------------------
__global__ void rescore_kernel(const float* __restrict__ X, const float* __restrict__ P) {
    unsigned int count = g_wcount;
    if (count > WCAP) count = WCAP;
    unsigned int total = count * 8u;
    for (unsigned int idx = blockIdx.x * 256 + threadIdx.x; idx < total;
         idx += gridDim.x * 256) {
        unsigned int e = idx >> 3;
        int c = (int)(idx & 7u);
        unsigned int w = g_wlist[e];
        int row = (int)(w >> 10);
        int grp = (int)(w & (NGRP - 1));
        int k0 = grp * 8;
        const float4* x4 = (const float4*)(X + (size_t)row * D_FIX);
        const float4* p4 = (const float4*)(P + (size_t)(k0 + c) * D_FIX);
        float acc = 0.0f;
        for (int d = 0; d < D_FIX / 4; d++) {
            float4 xv = x4[d];
            float4 pv = p4[d];
            acc = __fmaf_rn(xv.x, pv.x, acc);
            acc = __fmaf_rn(xv.y, pv.y, acc);
            acc = __fmaf_rn(xv.z, pv.z, acc);
            acc = __fmaf_rn(xv.w, pv.w, acc);
        }
        float t = __fadd_rn(g_xnorm[row], g_pnorm[k0 + c]);
        float dval = __fadd_rn(t, __fmul_rn(-2.0f, acc));
        unsigned long long key =
            ((unsigned long long)__float_as_uint(dval) << 32) | (unsigned)(k0 + c);
        atomicMin(&g_bestkey[row], key);
    }
}

// ---------------------------------------------------------------------------
// Kernel 6: gather + exact straight-through output + per-row loss partials.
// ---------------------------------------------------------------------------
__global__ void gather_loss_kernel(const float* __restrict__ X,
                                   const float* __restrict__ P,
                                   float* __restrict__ out) {
    int row = blockIdx.x;
    int t = threadIdx.x;
    int c = (int)(unsigned)(g_bestkey[row] & 0xFFFFFFFFull);
    const float* x = X + (size_t)row * D_FIX;
    const float* q = P + (size_t)c * D_FIX;
    float* o = out + (size_t)row * D_FIX;
    double s = 0.0;
#pragma unroll
    for (int i = 0; i < 4; i++) {
        int d = t + i * 128;
        float xv = x[d], qv = q[d];
        float diff = __fsub_rn(qv, xv);
        o[d] = __fadd_rn(xv, diff);
        s += (double)diff * (double)diff;
    }
#pragma unroll
    for (int o2 = 16; o2 > 0; o2 >>= 1) s += __shfl_down_sync(0xffffffffu, s, o2);
    __shared__ double sh[4];
    if ((t & 31) == 0) sh[t >> 5] = s;
    __syncthreads();
    if (t == 0) g_losspart[row] = sh[0] + sh[1] + sh[2] + sh[3];
}

// ---------------------------------------------------------------------------
// Kernel 7a: partial loss sums. 7b: final loss = fl(fl(mse*0.25) + mse).
// ---------------------------------------------------------------------------
__global__ void losssum_kernel() {
    __shared__ double sh[256];
    int t = threadIdx.x;
    sh[t] = g_losspart[blockIdx.x * 256 + t];
    __syncthreads();
    for (int o = 128; o > 0; o >>= 1) {
        if (t < o) sh[t] += sh[t + o];
        __syncthreads();
    }
    if (t == 0) g_losspart2[blockIdx.x] = sh[0];
}

__global__ void finalize_kernel(float* __restrict__ out,
                                long long tail_start, long long out_sz) {
    __shared__ double sh[128];
    int t = threadIdx.x;
    sh[t] = g_losspart2[t];
    __syncthreads();
    for (int o = 64; o > 0; o >>= 1) {
        if (t < o) sh[t] += sh[t + o];
        __syncthreads();
    }
    if (t == 0) {
        double mean = sh[0] / ((double)NR * (double)D_FIX);
        float m = (float)mean;
        float v = __fadd_rn(__fmul_rn(m, 0.25f), m);
        for (long long i = tail_start; i < out_sz; ++i) out[i] = v;
    }
}

// ---------------------------------------------------------------------------
extern "C" void kernel_launch(void* const* d_in, const int* in_sizes, int n_in,
                              void* d_out, int out_size) {
    const float* X = (const float*)d_in[0];
    const float* P = (const float*)d_in[1];
    float* out = (float*)d_out;

    cudaFuncSetAttribute(gemm_gmin_kernel,
                         cudaFuncAttributeMaxDynamicSharedMemorySize, SMEM_TOTAL);

    norms_kernel<<<NR + KP, 128>>>(X, P);    // also inits rowub/bestkey/wcount
    prep_kernel<<<(NR * NCH16 + KP * NCH16) / 256, 256>>>(X, P);
    gemm_gmin_kernel<<<RBLK * CBLK, 256, SMEM_TOTAL>>>();
    flag_kernel<<<NR / 64, 256>>>();
    rescore_kernel<<<1024, 256>>>(X, P);
    gather_loss_kernel<<<NR, 128>>>(X, P, out);
    losssum_kernel<<<128, 256>>>();
    finalize_kernel<<<1, 128>>>(out, (long long)NR * D_FIX, (long long)out_size);
}

// round 14
// speedup vs baseline: 1.7714x; 1.0032x over previous
#include <cuda_runtime.h>
#include <cuda_bf16.h>
#include <cstdint>

#define D_FIX 512
#define NR 32768
#define KP 8192
#define CTA_M 128
#define CTA_N 128
#define NCH16 32               // k tiles of 16
#define NCH32 16               // pipeline chunks of k32
#define RBLK (NR/CTA_M)        // 256
#define CBLK (KP/CTA_N)        // 64
#define NGRP (KP/8)            // 1024 groups of 8 cols
#define TILE_U 256             // 16B units per 4KB k16 tile
#define SMEM_STAGES (4*16384)  // 4 stages x 16KB (A 8KB + B 8KB)
#define SMEM_TOTAL  (SMEM_STAGES + 512 + 512)
#define MARGIN 1e-3f
#define WCAP (1u<<22)

// ---- device-global scratch (allocations forbidden) ----
__device__ uint4  g_A[(size_t)RBLK * NCH16 * TILE_U];    // 32MB (bf16 hi)
__device__ uint4  g_B[(size_t)CBLK * NCH16 * TILE_U];    // 8MB
__device__ float  g_xnorm[NR];
__device__ float  g_pnorm[KP];
__device__ float  g_gmin[(size_t)NGRP * NR];             // 128MB [group][row]
__device__ unsigned int g_rowub[NR];                     // approx row-min (bits)
__device__ unsigned long long g_bestkey[NR];
__device__ unsigned int g_wcount;
__device__ unsigned int g_wlist[WCAP];
__device__ double g_losspart[NR];
__device__ double g_losspart2[128];

// ---------------- PTX helpers (baseline sm_80-class only) ----------------
__device__ __forceinline__ uint32_t smem_u32(const void* p) {
    uint32_t a;
    asm("{ .reg .u64 t; cvta.to.shared.u64 t, %1; cvt.u32.u64 %0, t; }" : "=r"(a) : "l"(p));
    return a;
}
__device__ __forceinline__ void cp16(uint32_t dst, const void* src) {
    asm volatile("cp.async.cg.shared.global [%0], [%1], 16;" :: "r"(dst), "l"(src));
}
#define CP_COMMIT() asm volatile("cp.async.commit_group;")
#define CP_WAIT2()  asm volatile("cp.async.wait_group 2;")

#define LDSM4(r0, r1, r2, r3, addr) \
    asm volatile("ldmatrix.sync.aligned.m8n8.x4.shared.b16 {%0,%1,%2,%3}, [%4];" \
        : "=r"(r0), "=r"(r1), "=r"(r2), "=r"(r3) : "r"(addr))

#define MMA(c, a, b) \
    asm volatile("mma.sync.aligned.m16n8k16.row.col.f32.bf16.bf16.f32 " \
        "{%0,%1,%2,%3}, {%4,%5,%6,%7}, {%8,%9}, {%0,%1,%2,%3};" \
        : "+f"((c)[0]), "+f"((c)[1]), "+f"((c)[2]), "+f"((c)[3]) \
        : "r"((a)[0]), "r"((a)[1]), "r"((a)[2]), "r"((a)[3]), \
          "r"((b)[0]), "r"((b)[1]))

// ---------------------------------------------------------------------------
// Kernel 1: hi-bf16 convert, pre-swizzled tiled layout (validated R5-R12).
// unit(r, half) = r*2 + (half ^ ((r>>2)&1))  — conflict-free for ldmatrix.
// ---------------------------------------------------------------------------
__global__ void prep_kernel(const float* __restrict__ X, const float* __restrict__ P) {
    int gid = blockIdx.x * 256 + threadIdx.x;
    const int xcnt = NR * NCH16;
    bool isX = gid < xcnt;
    int g = isX ? gid : gid - xcnt;
    int row, chunk;
    if (isX) { row = g & (NR - 1); chunk = g >> 15; }
    else     { row = g & (KP - 1); chunk = g >> 13; }
    const float4* src = (const float4*)((isX ? X : P) + (size_t)row * D_FIX + chunk * 16);

    unsigned short hv[16];
#pragma unroll
    for (int i = 0; i < 4; i++) {
        float4 v = src[i];
        hv[i * 4 + 0] = __bfloat16_as_ushort(__float2bfloat16_rn(v.x));
        hv[i * 4 + 1] = __bfloat16_as_ushort(__float2bfloat16_rn(v.y));
        hv[i * 4 + 2] = __bfloat16_as_ushort(__float2bfloat16_rn(v.z));
        hv[i * 4 + 3] = __bfloat16_as_ushort(__float2bfloat16_rn(v.w));
    }
    int rin = row & 127;
    int blk = row >> 7;
    size_t base = (size_t)(blk * NCH16 + chunk) * TILE_U;
    int swz = (rin >> 2) & 1;
    uint4* dst = isX ? g_A : g_B;
    uint4 u0, u1;
    u0.x = hv[0]  | ((uint32_t)hv[1]  << 16);
    u0.y = hv[2]  | ((uint32_t)hv[3]  << 16);
    u0.z = hv[4]  | ((uint32_t)hv[5]  << 16);
    u0.w = hv[6]  | ((uint32_t)hv[7]  << 16);
    u1.x = hv[8]  | ((uint32_t)hv[9]  << 16);
    u1.y = hv[10] | ((uint32_t)hv[11] << 16);
    u1.z = hv[12] | ((uint32_t)hv[13] << 16);
    u1.w = hv[14] | ((uint32_t)hv[15] << 16);
    dst[base + rin * 2 + (0 ^ swz)] = u0;
    dst[base + rin * 2 + (1 ^ swz)] = u1;
}

// ---------------------------------------------------------------------------
// Kernel 2: row norms (double accumulate, one fp32 round — identical to R1)
// + init of rowub/bestkey/wcount.
// ---------------------------------------------------------------------------
__global__ void norms_kernel(const float* __restrict__ X, const float* __restrict__ P) {
    int row = blockIdx.x;
    const float* src = (row < NR) ? (X + (size_t)row * D_FIX)
                                  : (P + (size_t)(row - NR) * D_FIX);
    int t = threadIdx.x;
    double s = 0.0;
#pragma unroll
    for (int i = 0; i < 4; ++i) { float v = src[t + i * 128]; s += (double)v * (double)v; }
#pragma unroll
    for (int o = 16; o > 0; o >>= 1) s += __shfl_down_sync(0xffffffffu, s, o);
    __shared__ double sh[4];
    if ((t & 31) == 0) sh[t >> 5] = s;
    __syncthreads();
    if (t == 0) {
        float r = (float)(sh[0] + sh[1] + sh[2] + sh[3]);
        if (row < NR) {
            g_xnorm[row] = r;
            g_rowub[row] = 0x7F800000u;               // +inf
            g_bestkey[row] = 0xFFFFFFFFFFFFFFFFull;
            if (row == 0) g_wcount = 0;
        } else {
            g_pnorm[row - NR] = r;
        }
    }
}

// ---------------------------------------------------------------------------
// Kernel 3: HMMA bf16 (f32 accum) GEMM 128x128 + group-min epilogue +
// per-row atomicMin — byte-identical to R11/R12.
// ---------------------------------------------------------------------------
__device__ __forceinline__ void issue_stage(uint32_t sbase, int s, int tid,
                                            const uint4* aSrc, const uint4* bSrc) {
    uint32_t dst = sbase + (uint32_t)(s & 3) * 16384;
#pragma unroll
    for (int i = 0; i < 4; i++) {
        int u = tid + i * 256;
        const uint4* src = (u < 512) ? (aSrc + (size_t)s * 512 + u)
                                     : (bSrc + (size_t)s * 512 + (u - 512));
        cp16(dst + u * 16, src);
    }
}

__global__ __launch_bounds__(256, 2) void gemm_gmin_kernel() {
    extern __shared__ char smem[];
    uint32_t sb = smem_u32(smem);
    float* sAn = (float*)(smem + SMEM_STAGES);
    float* sPn = (float*)(smem + SMEM_STAGES + 512);

    const int tid = threadIdx.x;
    const int colblk = blockIdx.x & (CBLK - 1);
    const int rowblk = blockIdx.x >> 6;
    const int wid = tid >> 5, lane = tid & 31;
    const int wm = wid >> 2, wn = wid & 3;

    if (tid < 128) {
        sAn[tid] = g_xnorm[rowblk * CTA_M + tid];
        sPn[tid] = g_pnorm[colblk * CTA_N + tid];
    }

    const uint4* aSrc = g_A + (size_t)rowblk * NCH16 * TILE_U;
    const uint4* bSrc = g_B + (size_t)colblk * NCH16 * TILE_U;

    issue_stage(sb, 0, tid, aSrc, bSrc); CP_COMMIT();
    issue_stage(sb, 1, tid, aSrc, bSrc); CP_COMMIT();
    issue_stage(sb, 2, tid, aSrc, bSrc); CP_COMMIT();

    float c[4][4][4];
#pragma unroll
    for (int i = 0; i < 4; i++)
#pragma unroll
        for (int j = 0; j < 4; j++)
#pragma unroll
            for (int v = 0; v < 4; v++) c[i][j][v] = 0.0f;

    const int a_r = lane & 15;
    const int a_h = lane >> 4;
    const int b_r = (lane & 7) + ((lane >> 4) << 3);
    const int b_h = (lane >> 3) & 1;

    for (int s = 0; s < NCH32; s++) {
        CP_WAIT2();
        __syncthreads();
        if (s + 3 < NCH32) issue_stage(sb, s + 3, tid, aSrc, bSrc);
        CP_COMMIT();

        uint32_t stg = sb + (uint32_t)(s & 3) * 16384;
#pragma unroll
        for (int t = 0; t < 2; t++) {
            uint32_t sA = stg + t * 4096;
            uint32_t sB = stg + 8192 + t * 4096;

            uint32_t bf[4][2];
#pragma unroll
            for (int jj = 0; jj < 2; jj++) {
                int nrow = wn * 32 + jj * 16 + b_r;
                uint32_t addr = sB + nrow * 32 + ((b_h ^ ((nrow >> 2) & 1)) << 4);
                uint32_t r0, r1, r2, r3;
                LDSM4(r0, r1, r2, r3, addr);
                bf[jj * 2][0] = r0; bf[jj * 2][1] = r1;
                bf[jj * 2 + 1][0] = r2; bf[jj * 2 + 1][1] = r3;
            }
            uint32_t af[4][4];
#pragma unroll
            for (int i = 0; i < 4; i++) {
                int arow = wm * 64 + i * 16 + a_r;
                uint32_t addr = sA + arow * 32 + ((a_h ^ ((arow >> 2) & 1)) << 4);
                LDSM4(af[i][0], af[i][1], af[i][2], af[i][3], addr);
            }
#pragma unroll
            for (int i = 0; i < 4; i++)
#pragma unroll
                for (int j = 0; j < 4; j++)
                    MMA(c[i][j], af[i], bf[j]);
        }
    }

    // ---- epilogue: group mins + per-row running min -> atomicMin ----
    const int q = lane >> 2;
    float rub0[4], rub1[4];
#pragma unroll
    for (int i = 0; i < 4; i++) { rub0[i] = 3.402823466e38f; rub1[i] = 3.402823466e38f; }

#pragma unroll
    for (int i = 0; i < 4; i++) {
        int r0 = wm * 64 + i * 16 + q;
        float an0 = sAn[r0], an1 = sAn[r0 + 8];
#pragma unroll
        for (int j = 0; j < 4; j++) {
            int c0 = wn * 32 + j * 8 + (lane & 3) * 2;
            float pn0 = sPn[c0], pn1 = sPn[c0 + 1];
            float d00 = __fadd_rn(__fadd_rn(an0, pn0), __fmul_rn(-2.0f, c[i][j][0]));
            float d01 = __fadd_rn(__fadd_rn(an0, pn1), __fmul_rn(-2.0f, c[i][j][1]));
            float d10 = __fadd_rn(__fadd_rn(an1, pn0), __fmul_rn(-2.0f, c[i][j][2]));
            float d11 = __fadd_rn(__fadd_rn(an1, pn1), __fmul_rn(-2.0f, c[i][j][3]));
            float m0 = fminf(d00, d01);
            float m1 = fminf(d10, d11);
#pragma unroll
            for (int o = 1; o <= 2; o <<= 1) {
                m0 = fminf(m0, __shfl_xor_sync(0xffffffffu, m0, o));
                m1 = fminf(m1, __shfl_xor_sync(0xffffffffu, m1, o));
            }
            rub0[i] = fminf(rub0[i], m0);
            rub1[i] = fminf(rub1[i], m1);
            if ((lane & 3) == 0) {
                size_t gidx = (size_t)(colblk * 16 + wn * 4 + j) * NR
                            + rowblk * CTA_M + wm * 64 + i * 16;
                g_gmin[gidx + q] = m0;
                g_gmin[gidx + q + 8] = m1;
            }
        }
    }
    if ((lane & 3) == 0) {
#pragma unroll
        for (int i = 0; i < 4; i++) {
            int r0 = rowblk * CTA_M + wm * 64 + i * 16 + q;
            atomicMin(&g_rowub[r0], __float_as_uint(rub0[i]));
            atomicMin(&g_rowub[r0 + 8], __float_as_uint(rub1[i]));
        }
    }
}

// ---------------------------------------------------------------------------
// Kernel 4: flag groups within margin -> worklist. 8-wide load batches,
// ONE __any_sync per 8 slots (32 warp syncs total vs 1024); rare slow path
// does per-slot ballot + leader atomicAdd + popc-prefix scatter.
// ---------------------------------------------------------------------------
__global__ void flag_kernel() {
    int tid = threadIdx.x;
    int lane = tid & 31;
    int r = blockIdx.x * 64 + (tid & 63);
    int gl = tid >> 6;
    float thr = __uint_as_float(g_rowub[r]) + MARGIN;
    const float* col = g_gmin + (size_t)gl * 256 * NR + r;
    unsigned lt_mask = (1u << lane) - 1u;

    for (int g = 0; g < 256; g += 8) {
        float v[8];
#pragma unroll
        for (int o = 0; o < 8; o++) v[o] = col[(size_t)(g + o) * NR];
        bool any = false;
#pragma unroll
        for (int o = 0; o < 8; o++) any |= (v[o] <= thr);
        if (__any_sync(0xffffffffu, any)) {
#pragma unroll
            for (int o = 0; o < 8; o++) {
                unsigned mask = __ballot_sync(0xffffffffu, v[o] <= thr);
                if (mask) {
                    int leader = (int)(__ffs(mask) - 1);
                    unsigned base;
                    if (lane == leader)
                        base = atomicAdd(&g_wcount, (unsigned)__popc(mask));
                    base = __shfl_sync(0xffffffffu, base, leader);
                    if (v[o] <= thr) {
                        unsigned idx = base + (unsigned)__popc(mask & lt_mask);
                        if (idx < WCAP)
                            g_wlist[idx] = (unsigned)(r * NGRP + gl * 256 + g + o);
                    }
                }
            }
        }
    }
}

// ---------------------------------------------------------------------------
// Kernel 5: exact rescore — one thread per (entry, column). Per-column
// sequential fp32 FMA chain d=0..511 in the SAME order as R1/R5-R12;
// dist = fl(fl(an+pn) - 2*dot); u64 key atomicMin (commutative).
// ---------------------------------------------------------------------------
__global__ void rescore_kernel(const float* __restrict__ X, const float* __restrict__ P) {
    unsigned int count = g_wcount;
    if (count > WCAP) count = WCAP;
    unsigned int total = count * 8u;
    for (unsigned int idx = blockIdx.x * 256 + threadIdx.x; idx < total;
         idx += gridDim.x * 256) {
        unsigned int e = idx >> 3;
        int c = (int)(idx & 7u);
        unsigned int w = g_wlist[e];
        int row = (int)(w >> 10);
        int grp = (int)(w & (NGRP - 1));
        int k0 = grp * 8;
        const float4* x4 = (const float4*)(X + (size_t)row * D_FIX);
        const float4* p4 = (const float4*)(P + (size_t)(k0 + c) * D_FIX);
        float acc = 0.0f;
        for (int d = 0; d < D_FIX / 4; d++) {
            float4 xv = x4[d];
            float4 pv = p4[d];
            acc = __fmaf_rn(xv.x, pv.x, acc);
            acc = __fmaf_rn(xv.y, pv.y, acc);
            acc = __fmaf_rn(xv.z, pv.z, acc);
            acc = __fmaf_rn(xv.w, pv.w, acc);
        }
        float t = __fadd_rn(g_xnorm[row], g_pnorm[k0 + c]);
        float dval = __fadd_rn(t, __fmul_rn(-2.0f, acc));
        unsigned long long key =
            ((unsigned long long)__float_as_uint(dval) << 32) | (unsigned)(k0 + c);
        atomicMin(&g_bestkey[row], key);
    }
}

// ---------------------------------------------------------------------------
// Kernel 6: gather + exact straight-through output + per-row loss partials.
// ---------------------------------------------------------------------------
__global__ void gather_loss_kernel(const float* __restrict__ X,
                                   const float* __restrict__ P,
                                   float* __restrict__ out) {
    int row = blockIdx.x;
    int t = threadIdx.x;
    int c = (int)(unsigned)(g_bestkey[row] & 0xFFFFFFFFull);
    const float* x = X + (size_t)row * D_FIX;
    const float* q = P + (size_t)c * D_FIX;
    float* o = out + (size_t)row * D_FIX;
    double s = 0.0;
#pragma unroll
    for (int i = 0; i < 4; i++) {
        int d = t + i * 128;
        float xv = x[d], qv = q[d];
        float diff = __fsub_rn(qv, xv);
        o[d] = __fadd_rn(xv, diff);
        s += (double)diff * (double)diff;
    }
#pragma unroll
    for (int o2 = 16; o2 > 0; o2 >>= 1) s += __shfl_down_sync(0xffffffffu, s, o2);
    __shared__ double sh[4];
    if ((t & 31) == 0) sh[t >> 5] = s;
    __syncthreads();
    if (t == 0) g_losspart[row] = sh[0] + sh[1] + sh[2] + sh[3];
}

// ---------------------------------------------------------------------------
// Kernel 7a: partial loss sums. 7b: final loss = fl(fl(mse*0.25) + mse).
// ---------------------------------------------------------------------------
__global__ void losssum_kernel() {
    __shared__ double sh[256];
    int t = threadIdx.x;
    sh[t] = g_losspart[blockIdx.x * 256 + t];
    __syncthreads();
    for (int o = 128; o > 0; o >>= 1) {
        if (t < o) sh[t] += sh[t + o];
        __syncthreads();
    }
    if (t == 0) g_losspart2[blockIdx.x] = sh[0];
}

__global__ void finalize_kernel(float* __restrict__ out,
                                long long tail_start, long long out_sz) {
    __shared__ double sh[128];
    int t = threadIdx.x;
    sh[t] = g_losspart2[t];
    __syncthreads();
    for (int o = 64; o > 0; o >>= 1) {
        if (t < o) sh[t] += sh[t + o];
        __syncthreads();
    }
    if (t == 0) {
        double mean = sh[0] / ((double)NR * (double)D_FIX);
        float m = (float)mean;
        float v = __fadd_rn(__fmul_rn(m, 0.25f), m);
        for (long long i = tail_start; i < out_sz; ++i) out[i] = v;
    }
}

// ---------------------------------------------------------------------------
extern "C" void kernel_launch(void* const* d_in, const int* in_sizes, int n_in,
                              void* d_out, int out_size) {
    const float* X = (const float*)d_in[0];
    const float* P = (const float*)d_in[1];
    float* out = (float*)d_out;

    cudaFuncSetAttribute(gemm_gmin_kernel,
                         cudaFuncAttributeMaxDynamicSharedMemorySize, SMEM_TOTAL);

    norms_kernel<<<NR + KP, 128>>>(X, P);    // also inits rowub/bestkey/wcount
    prep_kernel<<<(NR * NCH16 + KP * NCH16) / 256, 256>>>(X, P);
    gemm_gmin_kernel<<<RBLK * CBLK, 256, SMEM_TOTAL>>>();
    flag_kernel<<<NR / 64, 256>>>();
    rescore_kernel<<<1024, 256>>>(X, P);
    gather_loss_kernel<<<NR, 128>>>(X, P, out);
    losssum_kernel<<<128, 256>>>();
    finalize_kernel<<<1, 128>>>(out, (long long)NR * D_FIX, (long long)out_size);
}

// round 15
// speedup vs baseline: 1.8491x; 1.0439x over previous
#include <cuda_runtime.h>
#include <cuda_bf16.h>
#include <cstdint>

#define D_FIX 512
#define NR 32768
#define KP 8192
#define CTA_M 128
#define CTA_N 128
#define NCH16 32               // k tiles of 16
#define NCH32 16               // pipeline chunks of k32
#define RBLK (NR/CTA_M)        // 256
#define CBLK (KP/CTA_N)        // 64
#define NGRP (KP/8)            // 1024 groups of 8 cols
#define TILE_U 256             // 16B units per 4KB k16 tile
#define SMEM_STAGES (4*16384)  // 4 stages x 16KB (A 8KB + B 8KB)
#define SMEM_TOTAL  (SMEM_STAGES + 512 + 512)
#define MARGIN 1e-3f
#define WCAP (1u<<22)

// ---- device-global scratch (allocations forbidden) ----
__device__ uint4  g_A[(size_t)RBLK * NCH16 * TILE_U];    // 32MB (bf16 hi)
__device__ uint4  g_B[(size_t)CBLK * NCH16 * TILE_U];    // 8MB
__device__ float  g_xnorm[NR];
__device__ float  g_pnorm[KP];
__device__ float  g_gmin[(size_t)NGRP * NR];             // 128MB [group][row]
__device__ unsigned int g_rowub[NR];                     // approx row-min (bits)
__device__ unsigned long long g_bestkey[NR];
__device__ unsigned int g_wcount;
__device__ unsigned int g_wlist[WCAP];
__device__ double g_losspart[NR];
__device__ double g_losspart2[128];

// ---------------- PTX helpers (baseline sm_80-class only) ----------------
__device__ __forceinline__ uint32_t smem_u32(const void* p) {
    uint32_t a;
    asm("{ .reg .u64 t; cvta.to.shared.u64 t, %1; cvt.u32.u64 %0, t; }" : "=r"(a) : "l"(p));
    return a;
}
__device__ __forceinline__ void cp16(uint32_t dst, const void* src) {
    asm volatile("cp.async.cg.shared.global [%0], [%1], 16;" :: "r"(dst), "l"(src));
}
#define CP_COMMIT() asm volatile("cp.async.commit_group;")
#define CP_WAIT2()  asm volatile("cp.async.wait_group 2;")

#define LDSM4(r0, r1, r2, r3, addr) \
    asm volatile("ldmatrix.sync.aligned.m8n8.x4.shared.b16 {%0,%1,%2,%3}, [%4];" \
        : "=r"(r0), "=r"(r1), "=r"(r2), "=r"(r3) : "r"(addr))

#define MMA(c, a, b) \
    asm volatile("mma.sync.aligned.m16n8k16.row.col.f32.bf16.bf16.f32 " \
        "{%0,%1,%2,%3}, {%4,%5,%6,%7}, {%8,%9}, {%0,%1,%2,%3};" \
        : "+f"((c)[0]), "+f"((c)[1]), "+f"((c)[2]), "+f"((c)[3]) \
        : "r"((a)[0]), "r"((a)[1]), "r"((a)[2]), "r"((a)[3]), \
          "r"((b)[0]), "r"((b)[1]))

// ---------------------------------------------------------------------------
// Kernel 1: hi-bf16 convert, pre-swizzled tiled layout (validated R5-R14).
// unit(r, half) = r*2 + (half ^ ((r>>2)&1))  — conflict-free for ldmatrix.
// ---------------------------------------------------------------------------
__global__ void prep_kernel(const float* __restrict__ X, const float* __restrict__ P) {
    int gid = blockIdx.x * 256 + threadIdx.x;
    const int xcnt = NR * NCH16;
    bool isX = gid < xcnt;
    int g = isX ? gid : gid - xcnt;
    int row, chunk;
    if (isX) { row = g & (NR - 1); chunk = g >> 15; }
    else     { row = g & (KP - 1); chunk = g >> 13; }
    const float4* src = (const float4*)((isX ? X : P) + (size_t)row * D_FIX + chunk * 16);

    unsigned short hv[16];
#pragma unroll
    for (int i = 0; i < 4; i++) {
        float4 v = src[i];
        hv[i * 4 + 0] = __bfloat16_as_ushort(__float2bfloat16_rn(v.x));
        hv[i * 4 + 1] = __bfloat16_as_ushort(__float2bfloat16_rn(v.y));
        hv[i * 4 + 2] = __bfloat16_as_ushort(__float2bfloat16_rn(v.z));
        hv[i * 4 + 3] = __bfloat16_as_ushort(__float2bfloat16_rn(v.w));
    }
    int rin = row & 127;
    int blk = row >> 7;
    size_t base = (size_t)(blk * NCH16 + chunk) * TILE_U;
    int swz = (rin >> 2) & 1;
    uint4* dst = isX ? g_A : g_B;
    uint4 u0, u1;
    u0.x = hv[0]  | ((uint32_t)hv[1]  << 16);
    u0.y = hv[2]  | ((uint32_t)hv[3]  << 16);
    u0.z = hv[4]  | ((uint32_t)hv[5]  << 16);
    u0.w = hv[6]  | ((uint32_t)hv[7]  << 16);
    u1.x = hv[8]  | ((uint32_t)hv[9]  << 16);
    u1.y = hv[10] | ((uint32_t)hv[11] << 16);
    u1.z = hv[12] | ((uint32_t)hv[13] << 16);
    u1.w = hv[14] | ((uint32_t)hv[15] << 16);
    dst[base + rin * 2 + (0 ^ swz)] = u0;
    dst[base + rin * 2 + (1 ^ swz)] = u1;
}

// ---------------------------------------------------------------------------
// Kernel 2: row norms (double accumulate, one fp32 round — identical to R1)
// + init of rowub/bestkey/wcount.
// ---------------------------------------------------------------------------
__global__ void norms_kernel(const float* __restrict__ X, const float* __restrict__ P) {
    int row = blockIdx.x;
    const float* src = (row < NR) ? (X + (size_t)row * D_FIX)
                                  : (P + (size_t)(row - NR) * D_FIX);
    int t = threadIdx.x;
    double s = 0.0;
#pragma unroll
    for (int i = 0; i < 4; ++i) { float v = src[t + i * 128]; s += (double)v * (double)v; }
#pragma unroll
    for (int o = 16; o > 0; o >>= 1) s += __shfl_down_sync(0xffffffffu, s, o);
    __shared__ double sh[4];
    if ((t & 31) == 0) sh[t >> 5] = s;
    __syncthreads();
    if (t == 0) {
        float r = (float)(sh[0] + sh[1] + sh[2] + sh[3]);
        if (row < NR) {
            g_xnorm[row] = r;
            g_rowub[row] = 0x7F800000u;               // +inf
            g_bestkey[row] = 0xFFFFFFFFFFFFFFFFull;
            if (row == 0) g_wcount = 0;
        } else {
            g_pnorm[row - NR] = r;
        }
    }
}

// ---------------------------------------------------------------------------
// Kernel 3: HMMA bf16 (f32 accum) GEMM 128x128 + group-min epilogue +
// per-row atomicMin — byte-identical to R11-R14.
// ---------------------------------------------------------------------------
__device__ __forceinline__ void issue_stage(uint32_t sbase, int s, int tid,
                                            const uint4* aSrc, const uint4* bSrc) {
    uint32_t dst = sbase + (uint32_t)(s & 3) * 16384;
#pragma unroll
    for (int i = 0; i < 4; i++) {
        int u = tid + i * 256;
        const uint4* src = (u < 512) ? (aSrc + (size_t)s * 512 + u)
                                     : (bSrc + (size_t)s * 512 + (u - 512));
        cp16(dst + u * 16, src);
    }
}

__global__ __launch_bounds__(256, 2) void gemm_gmin_kernel() {
    extern __shared__ char smem[];
    uint32_t sb = smem_u32(smem);
    float* sAn = (float*)(smem + SMEM_STAGES);
    float* sPn = (float*)(smem + SMEM_STAGES + 512);

    const int tid = threadIdx.x;
    const int colblk = blockIdx.x & (CBLK - 1);
    const int rowblk = blockIdx.x >> 6;
    const int wid = tid >> 5, lane = tid & 31;
    const int wm = wid >> 2, wn = wid & 3;

    if (tid < 128) {
        sAn[tid] = g_xnorm[rowblk * CTA_M + tid];
        sPn[tid] = g_pnorm[colblk * CTA_N + tid];
    }

    const uint4* aSrc = g_A + (size_t)rowblk * NCH16 * TILE_U;
    const uint4* bSrc = g_B + (size_t)colblk * NCH16 * TILE_U;

    issue_stage(sb, 0, tid, aSrc, bSrc); CP_COMMIT();
    issue_stage(sb, 1, tid, aSrc, bSrc); CP_COMMIT();
    issue_stage(sb, 2, tid, aSrc, bSrc); CP_COMMIT();

    float c[4][4][4];
#pragma unroll
    for (int i = 0; i < 4; i++)
#pragma unroll
        for (int j = 0; j < 4; j++)
#pragma unroll
            for (int v = 0; v < 4; v++) c[i][j][v] = 0.0f;

    const int a_r = lane & 15;
    const int a_h = lane >> 4;
    const int b_r = (lane & 7) + ((lane >> 4) << 3);
    const int b_h = (lane >> 3) & 1;

    for (int s = 0; s < NCH32; s++) {
        CP_WAIT2();
        __syncthreads();
        if (s + 3 < NCH32) issue_stage(sb, s + 3, tid, aSrc, bSrc);
        CP_COMMIT();

        uint32_t stg = sb + (uint32_t)(s & 3) * 16384;
#pragma unroll
        for (int t = 0; t < 2; t++) {
            uint32_t sA = stg + t * 4096;
            uint32_t sB = stg + 8192 + t * 4096;

            uint32_t bf[4][2];
#pragma unroll
            for (int jj = 0; jj < 2; jj++) {
                int nrow = wn * 32 + jj * 16 + b_r;
                uint32_t addr = sB + nrow * 32 + ((b_h ^ ((nrow >> 2) & 1)) << 4);
                uint32_t r0, r1, r2, r3;
                LDSM4(r0, r1, r2, r3, addr);
                bf[jj * 2][0] = r0; bf[jj * 2][1] = r1;
                bf[jj * 2 + 1][0] = r2; bf[jj * 2 + 1][1] = r3;
            }
            uint32_t af[4][4];
#pragma unroll
            for (int i = 0; i < 4; i++) {
                int arow = wm * 64 + i * 16 + a_r;
                uint32_t addr = sA + arow * 32 + ((a_h ^ ((arow >> 2) & 1)) << 4);
                LDSM4(af[i][0], af[i][1], af[i][2], af[i][3], addr);
            }
#pragma unroll
            for (int i = 0; i < 4; i++)
#pragma unroll
                for (int j = 0; j < 4; j++)
                    MMA(c[i][j], af[i], bf[j]);
        }
    }

    // ---- epilogue: group mins + per-row running min -> atomicMin ----
    const int q = lane >> 2;
    float rub0[4], rub1[4];
#pragma unroll
    for (int i = 0; i < 4; i++) { rub0[i] = 3.402823466e38f; rub1[i] = 3.402823466e38f; }

#pragma unroll
    for (int i = 0; i < 4; i++) {
        int r0 = wm * 64 + i * 16 + q;
        float an0 = sAn[r0], an1 = sAn[r0 + 8];
#pragma unroll
        for (int j = 0; j < 4; j++) {
            int c0 = wn * 32 + j * 8 + (lane & 3) * 2;
            float pn0 = sPn[c0], pn1 = sPn[c0 + 1];
            float d00 = __fadd_rn(__fadd_rn(an0, pn0), __fmul_rn(-2.0f, c[i][j][0]));
            float d01 = __fadd_rn(__fadd_rn(an0, pn1), __fmul_rn(-2.0f, c[i][j][1]));
            float d10 = __fadd_rn(__fadd_rn(an1, pn0), __fmul_rn(-2.0f, c[i][j][2]));
            float d11 = __fadd_rn(__fadd_rn(an1, pn1), __fmul_rn(-2.0f, c[i][j][3]));
            float m0 = fminf(d00, d01);
            float m1 = fminf(d10, d11);
#pragma unroll
            for (int o = 1; o <= 2; o <<= 1) {
                m0 = fminf(m0, __shfl_xor_sync(0xffffffffu, m0, o));
                m1 = fminf(m1, __shfl_xor_sync(0xffffffffu, m1, o));
            }
            rub0[i] = fminf(rub0[i], m0);
            rub1[i] = fminf(rub1[i], m1);
            if ((lane & 3) == 0) {
                size_t gidx = (size_t)(colblk * 16 + wn * 4 + j) * NR
                            + rowblk * CTA_M + wm * 64 + i * 16;
                g_gmin[gidx + q] = m0;
                g_gmin[gidx + q + 8] = m1;
            }
        }
    }
    if ((lane & 3) == 0) {
#pragma unroll
        for (int i = 0; i < 4; i++) {
            int r0 = rowblk * CTA_M + wm * 64 + i * 16 + q;
            atomicMin(&g_rowub[r0], __float_as_uint(rub0[i]));
            atomicMin(&g_rowub[r0 + 8], __float_as_uint(rub1[i]));
        }
    }
}

// ---------------------------------------------------------------------------
// Kernel 4: flag groups within margin -> worklist. BRANCHLESS hot loop:
// 2048 CTAs (64 rows x 4 group-lanes; 64 groups/thread = u64 bitmask),
// predicated mask accumulate, cold postlude appends via one atomicAdd.
// ---------------------------------------------------------------------------
__global__ void flag_kernel() {
    int tid = threadIdx.x;
    int rb = blockIdx.x >> 2;            // 0..511
    int gb = blockIdx.x & 3;             // 0..3
    int r = rb * 64 + (tid & 63);
    int gl = tid >> 6;                   // 0..3
    int gbase = gb * 256 + gl * 64;
    float thr = __uint_as_float(g_rowub[r]) + MARGIN;
    const float* col = g_gmin + (size_t)gbase * NR + r;

    unsigned long long mask = 0ull;
    for (int g = 0; g < 64; g += 8) {
        float v[8];
#pragma unroll
        for (int o = 0; o < 8; o++) v[o] = col[(size_t)(g + o) * NR];
#pragma unroll
        for (int o = 0; o < 8; o++)
            if (v[o] <= thr) mask |= 1ull << (g + o);
    }
    if (mask) {
        unsigned base = atomicAdd(&g_wcount, (unsigned)__popcll(mask));
        unsigned rg = (unsigned)(r * NGRP + gbase);
        while (mask) {
            int b = (int)(__ffsll(mask) - 1);
            mask &= mask - 1;
            if (base < WCAP) g_wlist[base] = rg + (unsigned)b;
            base++;
        }
    }
}

// ---------------------------------------------------------------------------
// Kernel 5: exact rescore — one thread per (entry, column). Per-column
// sequential fp32 FMA chain d=0..511 in the SAME order as R1/R5-R14;
// dist = fl(fl(an+pn) - 2*dot); u64 key atomicMin (commutative).
// ---------------------------------------------------------------------------
__global__ void rescore_kernel(const float* __restrict__ X, const float* __restrict__ P) {
    unsigned int count = g_wcount;
    if (count > WCAP) count = WCAP;
    unsigned int total = count * 8u;
    for (unsigned int idx = blockIdx.x * 256 + threadIdx.x; idx < total;
         idx += gridDim.x * 256) {
        unsigned int e = idx >> 3;
        int c = (int)(idx & 7u);
        unsigned int w = g_wlist[e];
        int row = (int)(w >> 10);
        int grp = (int)(w & (NGRP - 1));
        int k0 = grp * 8;
        const float4* x4 = (const float4*)(X + (size_t)row * D_FIX);
        const float4* p4 = (const float4*)(P + (size_t)(k0 + c) * D_FIX);
        float acc = 0.0f;
        for (int d = 0; d < D_FIX / 4; d++) {
            float4 xv = x4[d];
            float4 pv = p4[d];
            acc = __fmaf_rn(xv.x, pv.x, acc);
            acc = __fmaf_rn(xv.y, pv.y, acc);
            acc = __fmaf_rn(xv.z, pv.z, acc);
            acc = __fmaf_rn(xv.w, pv.w, acc);
        }
        float t = __fadd_rn(g_xnorm[row], g_pnorm[k0 + c]);
        float dval = __fadd_rn(t, __fmul_rn(-2.0f, acc));
        unsigned long long key =
            ((unsigned long long)__float_as_uint(dval) << 32) | (unsigned)(k0 + c);
        atomicMin(&g_bestkey[row], key);
    }
}

// ---------------------------------------------------------------------------
// Kernel 6: gather + exact straight-through output + per-row loss partials.
// ---------------------------------------------------------------------------
__global__ void gather_loss_kernel(const float* __restrict__ X,
                                   const float* __restrict__ P,
                                   float* __restrict__ out) {
    int row = blockIdx.x;
    int t = threadIdx.x;
    int c = (int)(unsigned)(g_bestkey[row] & 0xFFFFFFFFull);
    const float* x = X + (size_t)row * D_FIX;
    const float* q = P + (size_t)c * D_FIX;
    float* o = out + (size_t)row * D_FIX;
    double s = 0.0;
#pragma unroll
    for (int i = 0; i < 4; i++) {
        int d = t + i * 128;
        float xv = x[d], qv = q[d];
        float diff = __fsub_rn(qv, xv);
        o[d] = __fadd_rn(xv, diff);
        s += (double)diff * (double)diff;
    }
#pragma unroll
    for (int o2 = 16; o2 > 0; o2 >>= 1) s += __shfl_down_sync(0xffffffffu, s, o2);
    __shared__ double sh[4];
    if ((t & 31) == 0) sh[t >> 5] = s;
    __syncthreads();
    if (t == 0) g_losspart[row] = sh[0] + sh[1] + sh[2] + sh[3];
}

// ---------------------------------------------------------------------------
// Kernel 7a: partial loss sums. 7b: final loss = fl(fl(mse*0.25) + mse).
// ---------------------------------------------------------------------------
__global__ void losssum_kernel() {
    __shared__ double sh[256];
    int t = threadIdx.x;
    sh[t] = g_losspart[blockIdx.x * 256 + t];
    __syncthreads();
    for (int o = 128; o > 0; o >>= 1) {
        if (t < o) sh[t] += sh[t + o];
        __syncthreads();
    }
    if (t == 0) g_losspart2[blockIdx.x] = sh[0];
}

__global__ void finalize_kernel(float* __restrict__ out,
                                long long tail_start, long long out_sz) {
    __shared__ double sh[128];
    int t = threadIdx.x;
    sh[t] = g_losspart2[t];
    __syncthreads();
    for (int o = 64; o > 0; o >>= 1) {
        if (t < o) sh[t] += sh[t + o];
        __syncthreads();
    }
    if (t == 0) {
        double mean = sh[0] / ((double)NR * (double)D_FIX);
        float m = (float)mean;
        float v = __fadd_rn(__fmul_rn(m, 0.25f), m);
        for (long long i = tail_start; i < out_sz; ++i) out[i] = v;
    }
}

// ---------------------------------------------------------------------------
extern "C" void kernel_launch(void* const* d_in, const int* in_sizes, int n_in,
                              void* d_out, int out_size) {
    const float* X = (const float*)d_in[0];
    const float* P = (const float*)d_in[1];
    float* out = (float*)d_out;

    cudaFuncSetAttribute(gemm_gmin_kernel,
                         cudaFuncAttributeMaxDynamicSharedMemorySize, SMEM_TOTAL);

    norms_kernel<<<NR + KP, 128>>>(X, P);    // also inits rowub/bestkey/wcount
    prep_kernel<<<(NR * NCH16 + KP * NCH16) / 256, 256>>>(X, P);
    gemm_gmin_kernel<<<RBLK * CBLK, 256, SMEM_TOTAL>>>();
    flag_kernel<<<(NR / 64) * 4, 256>>>();
    rescore_kernel<<<1024, 256>>>(X, P);
    gather_loss_kernel<<<NR, 128>>>(X, P, out);
    losssum_kernel<<<128, 256>>>();
    finalize_kernel<<<1, 128>>>(out, (long long)NR * D_FIX, (long long)out_size);
}

// round 16
// speedup vs baseline: 1.8525x; 1.0018x over previous
#include <cuda_runtime.h>
#include <cuda_bf16.h>
#include <cstdint>

#define D_FIX 512
#define NR 32768
#define KP 8192
#define CTA_M 128
#define CTA_N 128
#define NCH16 32               // k tiles of 16
#define NCH32 16               // pipeline chunks of k32
#define RBLK (NR/CTA_M)        // 256
#define CBLK (KP/CTA_N)        // 64
#define NGRP (KP/8)            // 1024 groups of 8 cols
#define TILE_U 256             // 16B units per 4KB k16 tile
#define SMEM_STAGES (4*16384)  // 4 stages x 16KB (A 8KB + B 8KB)
#define SMEM_TOTAL  (SMEM_STAGES + 512 + 512)
#define MARGIN 1e-3f
#define WCAP (1u<<22)

// ---- device-global scratch (allocations forbidden) ----
__device__ uint4  g_A[(size_t)RBLK * NCH16 * TILE_U];    // 32MB (bf16 hi)
__device__ uint4  g_B[(size_t)CBLK * NCH16 * TILE_U];    // 8MB
__device__ float  g_xnorm[NR];
__device__ float  g_pnorm[KP];
__device__ float  g_gmin[(size_t)NGRP * NR];             // 128MB [group][row]
__device__ unsigned int g_rowub[NR];                     // approx row-min (bits)
__device__ unsigned long long g_bestkey[NR];
__device__ unsigned int g_wcount;
__device__ unsigned int g_wlist[WCAP];
__device__ double g_losspart[NR];
__device__ double g_losspart2[128];

// ---------------- PTX helpers (baseline sm_80-class only) ----------------
__device__ __forceinline__ uint32_t smem_u32(const void* p) {
    uint32_t a;
    asm("{ .reg .u64 t; cvta.to.shared.u64 t, %1; cvt.u32.u64 %0, t; }" : "=r"(a) : "l"(p));
    return a;
}
__device__ __forceinline__ void cp16(uint32_t dst, const void* src) {
    asm volatile("cp.async.cg.shared.global [%0], [%1], 16;" :: "r"(dst), "l"(src));
}
#define CP_COMMIT() asm volatile("cp.async.commit_group;")
#define CP_WAIT2()  asm volatile("cp.async.wait_group 2;")

#define LDSM4(r0, r1, r2, r3, addr) \
    asm volatile("ldmatrix.sync.aligned.m8n8.x4.shared.b16 {%0,%1,%2,%3}, [%4];" \
        : "=r"(r0), "=r"(r1), "=r"(r2), "=r"(r3) : "r"(addr))

#define MMA(c, a, b) \
    asm volatile("mma.sync.aligned.m16n8k16.row.col.f32.bf16.bf16.f32 " \
        "{%0,%1,%2,%3}, {%4,%5,%6,%7}, {%8,%9}, {%0,%1,%2,%3};" \
        : "+f"((c)[0]), "+f"((c)[1]), "+f"((c)[2]), "+f"((c)[3]) \
        : "r"((a)[0]), "r"((a)[1]), "r"((a)[2]), "r"((a)[3]), \
          "r"((b)[0]), "r"((b)[1]))

// ---------------------------------------------------------------------------
// Kernel 1: hi-bf16 convert, pre-swizzled tiled layout (validated R5-R15).
// unit(r, half) = r*2 + (half ^ ((r>>2)&1))  — conflict-free for ldmatrix.
// ---------------------------------------------------------------------------
__global__ void prep_kernel(const float* __restrict__ X, const float* __restrict__ P) {
    int gid = blockIdx.x * 256 + threadIdx.x;
    const int xcnt = NR * NCH16;
    bool isX = gid < xcnt;
    int g = isX ? gid : gid - xcnt;
    int row, chunk;
    if (isX) { row = g & (NR - 1); chunk = g >> 15; }
    else     { row = g & (KP - 1); chunk = g >> 13; }
    const float4* src = (const float4*)((isX ? X : P) + (size_t)row * D_FIX + chunk * 16);

    unsigned short hv[16];
#pragma unroll
    for (int i = 0; i < 4; i++) {
        float4 v = src[i];
        hv[i * 4 + 0] = __bfloat16_as_ushort(__float2bfloat16_rn(v.x));
        hv[i * 4 + 1] = __bfloat16_as_ushort(__float2bfloat16_rn(v.y));
        hv[i * 4 + 2] = __bfloat16_as_ushort(__float2bfloat16_rn(v.z));
        hv[i * 4 + 3] = __bfloat16_as_ushort(__float2bfloat16_rn(v.w));
    }
    int rin = row & 127;
    int blk = row >> 7;
    size_t base = (size_t)(blk * NCH16 + chunk) * TILE_U;
    int swz = (rin >> 2) & 1;
    uint4* dst = isX ? g_A : g_B;
    uint4 u0, u1;
    u0.x = hv[0]  | ((uint32_t)hv[1]  << 16);
    u0.y = hv[2]  | ((uint32_t)hv[3]  << 16);
    u0.z = hv[4]  | ((uint32_t)hv[5]  << 16);
    u0.w = hv[6]  | ((uint32_t)hv[7]  << 16);
    u1.x = hv[8]  | ((uint32_t)hv[9]  << 16);
    u1.y = hv[10] | ((uint32_t)hv[11] << 16);
    u1.z = hv[12] | ((uint32_t)hv[13] << 16);
    u1.w = hv[14] | ((uint32_t)hv[15] << 16);
    dst[base + rin * 2 + (0 ^ swz)] = u0;
    dst[base + rin * 2 + (1 ^ swz)] = u1;
}

// ---------------------------------------------------------------------------
// Kernel 2: row norms (double accumulate, one fp32 round — identical to R1)
// + init of rowub/bestkey/wcount.
// ---------------------------------------------------------------------------
__global__ void norms_kernel(const float* __restrict__ X, const float* __restrict__ P) {
    int row = blockIdx.x;
    const float* src = (row < NR) ? (X + (size_t)row * D_FIX)
                                  : (P + (size_t)(row - NR) * D_FIX);
    int t = threadIdx.x;
    double s = 0.0;
#pragma unroll
    for (int i = 0; i < 4; ++i) { float v = src[t + i * 128]; s += (double)v * (double)v; }
#pragma unroll
    for (int o = 16; o > 0; o >>= 1) s += __shfl_down_sync(0xffffffffu, s, o);
    __shared__ double sh[4];
    if ((t & 31) == 0) sh[t >> 5] = s;
    __syncthreads();
    if (t == 0) {
        float r = (float)(sh[0] + sh[1] + sh[2] + sh[3]);
        if (row < NR) {
            g_xnorm[row] = r;
            g_rowub[row] = 0x7F800000u;               // +inf
            g_bestkey[row] = 0xFFFFFFFFFFFFFFFFull;
            if (row == 0) g_wcount = 0;
        } else {
            g_pnorm[row - NR] = r;
        }
    }
}

// ---------------------------------------------------------------------------
// Kernel 3: HMMA bf16 (f32 accum) GEMM 128x128 + group-min epilogue +
// per-row atomicMin — byte-identical to R11-R15.
// ---------------------------------------------------------------------------
__device__ __forceinline__ void issue_stage(uint32_t sbase, int s, int tid,
                                            const uint4* aSrc, const uint4* bSrc) {
    uint32_t dst = sbase + (uint32_t)(s & 3) * 16384;
#pragma unroll
    for (int i = 0; i < 4; i++) {
        int u = tid + i * 256;
        const uint4* src = (u < 512) ? (aSrc + (size_t)s * 512 + u)
                                     : (bSrc + (size_t)s * 512 + (u - 512));
        cp16(dst + u * 16, src);
    }
}

__global__ __launch_bounds__(256, 2) void gemm_gmin_kernel() {
    extern __shared__ char smem[];
    uint32_t sb = smem_u32(smem);
    float* sAn = (float*)(smem + SMEM_STAGES);
    float* sPn = (float*)(smem + SMEM_STAGES + 512);

    const int tid = threadIdx.x;
    const int colblk = blockIdx.x & (CBLK - 1);
    const int rowblk = blockIdx.x >> 6;
    const int wid = tid >> 5, lane = tid & 31;
    const int wm = wid >> 2, wn = wid & 3;

    if (tid < 128) {
        sAn[tid] = g_xnorm[rowblk * CTA_M + tid];
        sPn[tid] = g_pnorm[colblk * CTA_N + tid];
    }

    const uint4* aSrc = g_A + (size_t)rowblk * NCH16 * TILE_U;
    const uint4* bSrc = g_B + (size_t)colblk * NCH16 * TILE_U;

    issue_stage(sb, 0, tid, aSrc, bSrc); CP_COMMIT();
    issue_stage(sb, 1, tid, aSrc, bSrc); CP_COMMIT();
    issue_stage(sb, 2, tid, aSrc, bSrc); CP_COMMIT();

    float c[4][4][4];
#pragma unroll
    for (int i = 0; i < 4; i++)
#pragma unroll
        for (int j = 0; j < 4; j++)
#pragma unroll
            for (int v = 0; v < 4; v++) c[i][j][v] = 0.0f;

    const int a_r = lane & 15;
    const int a_h = lane >> 4;
    const int b_r = (lane & 7) + ((lane >> 4) << 3);
    const int b_h = (lane >> 3) & 1;

    for (int s = 0; s < NCH32; s++) {
        CP_WAIT2();
        __syncthreads();
        if (s + 3 < NCH32) issue_stage(sb, s + 3, tid, aSrc, bSrc);
        CP_COMMIT();

        uint32_t stg = sb + (uint32_t)(s & 3) * 16384;
#pragma unroll
        for (int t = 0; t < 2; t++) {
            uint32_t sA = stg + t * 4096;
            uint32_t sB = stg + 8192 + t * 4096;

            uint32_t bf[4][2];
#pragma unroll
            for (int jj = 0; jj < 2; jj++) {
                int nrow = wn * 32 + jj * 16 + b_r;
                uint32_t addr = sB + nrow * 32 + ((b_h ^ ((nrow >> 2) & 1)) << 4);
                uint32_t r0, r1, r2, r3;
                LDSM4(r0, r1, r2, r3, addr);
                bf[jj * 2][0] = r0; bf[jj * 2][1] = r1;
                bf[jj * 2 + 1][0] = r2; bf[jj * 2 + 1][1] = r3;
            }
            uint32_t af[4][4];
#pragma unroll
            for (int i = 0; i < 4; i++) {
                int arow = wm * 64 + i * 16 + a_r;
                uint32_t addr = sA + arow * 32 + ((a_h ^ ((arow >> 2) & 1)) << 4);
                LDSM4(af[i][0], af[i][1], af[i][2], af[i][3], addr);
            }
#pragma unroll
            for (int i = 0; i < 4; i++)
#pragma unroll
                for (int j = 0; j < 4; j++)
                    MMA(c[i][j], af[i], bf[j]);
        }
    }

    // ---- epilogue: group mins + per-row running min -> atomicMin ----
    const int q = lane >> 2;
    float rub0[4], rub1[4];
#pragma unroll
    for (int i = 0; i < 4; i++) { rub0[i] = 3.402823466e38f; rub1[i] = 3.402823466e38f; }

#pragma unroll
    for (int i = 0; i < 4; i++) {
        int r0 = wm * 64 + i * 16 + q;
        float an0 = sAn[r0], an1 = sAn[r0 + 8];
#pragma unroll
        for (int j = 0; j < 4; j++) {
            int c0 = wn * 32 + j * 8 + (lane & 3) * 2;
            float pn0 = sPn[c0], pn1 = sPn[c0 + 1];
            float d00 = __fadd_rn(__fadd_rn(an0, pn0), __fmul_rn(-2.0f, c[i][j][0]));
            float d01 = __fadd_rn(__fadd_rn(an0, pn1), __fmul_rn(-2.0f, c[i][j][1]));
            float d10 = __fadd_rn(__fadd_rn(an1, pn0), __fmul_rn(-2.0f, c[i][j][2]));
            float d11 = __fadd_rn(__fadd_rn(an1, pn1), __fmul_rn(-2.0f, c[i][j][3]));
            float m0 = fminf(d00, d01);
            float m1 = fminf(d10, d11);
#pragma unroll
            for (int o = 1; o <= 2; o <<= 1) {
                m0 = fminf(m0, __shfl_xor_sync(0xffffffffu, m0, o));
                m1 = fminf(m1, __shfl_xor_sync(0xffffffffu, m1, o));
            }
            rub0[i] = fminf(rub0[i], m0);
            rub1[i] = fminf(rub1[i], m1);
            if ((lane & 3) == 0) {
                size_t gidx = (size_t)(colblk * 16 + wn * 4 + j) * NR
                            + rowblk * CTA_M + wm * 64 + i * 16;
                g_gmin[gidx + q] = m0;
                g_gmin[gidx + q + 8] = m1;
            }
        }
    }
    if ((lane & 3) == 0) {
#pragma unroll
        for (int i = 0; i < 4; i++) {
            int r0 = rowblk * CTA_M + wm * 64 + i * 16 + q;
            atomicMin(&g_rowub[r0], __float_as_uint(rub0[i]));
            atomicMin(&g_rowub[r0 + 8], __float_as_uint(rub1[i]));
        }
    }
}

// ---------------------------------------------------------------------------
// Kernel 4: flag groups within margin -> worklist. float4-over-rows:
// thread = (row-quad, 64-group lane); 64 float4 loads (4x fewer LDGs),
// branchless per-row u64 masks, cold postlude appends via atomicAdd.
// ---------------------------------------------------------------------------
__global__ void flag_kernel() {
    int tid = threadIdx.x;
    int rq = blockIdx.x * 16 + (tid & 15);   // row-quad 0..8191
    int gl = tid >> 4;                       // 0..15 (64 groups each)
    int r = rq * 4;
    int gbase = gl * 64;
    float thr0 = __uint_as_float(g_rowub[r + 0]) + MARGIN;
    float thr1 = __uint_as_float(g_rowub[r + 1]) + MARGIN;
    float thr2 = __uint_as_float(g_rowub[r + 2]) + MARGIN;
    float thr3 = __uint_as_float(g_rowub[r + 3]) + MARGIN;
    const float4* col = (const float4*)(g_gmin + (size_t)gbase * NR + r);
    const size_t gstride = NR / 4;

    unsigned long long m0 = 0ull, m1 = 0ull, m2 = 0ull, m3 = 0ull;
    for (int g = 0; g < 64; g += 8) {
        float4 v[8];
#pragma unroll
        for (int o = 0; o < 8; o++) v[o] = col[(size_t)(g + o) * gstride];
#pragma unroll
        for (int o = 0; o < 8; o++) {
            unsigned long long bit = 1ull << (g + o);
            if (v[o].x <= thr0) m0 |= bit;
            if (v[o].y <= thr1) m1 |= bit;
            if (v[o].z <= thr2) m2 |= bit;
            if (v[o].w <= thr3) m3 |= bit;
        }
    }
#pragma unroll
    for (int rr = 0; rr < 4; rr++) {
        unsigned long long mask = (rr == 0) ? m0 : (rr == 1) ? m1 : (rr == 2) ? m2 : m3;
        if (mask) {
            unsigned base = atomicAdd(&g_wcount, (unsigned)__popcll(mask));
            unsigned rg = (unsigned)((r + rr) * NGRP + gbase);
            while (mask) {
                int b = (int)(__ffsll(mask) - 1);
                mask &= mask - 1;
                if (base < WCAP) g_wlist[base] = rg + (unsigned)b;
                base++;
            }
        }
    }
}

// ---------------------------------------------------------------------------
// Kernel 5: exact rescore — one thread per (entry, column). Per-column
// sequential fp32 FMA chain d=0..511 in the SAME order as R1/R5-R15;
// dist = fl(fl(an+pn) - 2*dot); u64 key atomicMin (commutative).
// ---------------------------------------------------------------------------
__global__ void rescore_kernel(const float* __restrict__ X, const float* __restrict__ P) {
    unsigned int count = g_wcount;
    if (count > WCAP) count = WCAP;
    unsigned int total = count * 8u;
    for (unsigned int idx = blockIdx.x * 256 + threadIdx.x; idx < total;
         idx += gridDim.x * 256) {
        unsigned int e = idx >> 3;
        int c = (int)(idx & 7u);
        unsigned int w = g_wlist[e];
        int row = (int)(w >> 10);
        int grp = (int)(w & (NGRP - 1));
        int k0 = grp * 8;
        const float4* x4 = (const float4*)(X + (size_t)row * D_FIX);
        const float4* p4 = (const float4*)(P + (size_t)(k0 + c) * D_FIX);
        float acc = 0.0f;
        for (int d = 0; d < D_FIX / 4; d++) {
            float4 xv = x4[d];
            float4 pv = p4[d];
            acc = __fmaf_rn(xv.x, pv.x, acc);
            acc = __fmaf_rn(xv.y, pv.y, acc);
            acc = __fmaf_rn(xv.z, pv.z, acc);
            acc = __fmaf_rn(xv.w, pv.w, acc);
        }
        float t = __fadd_rn(g_xnorm[row], g_pnorm[k0 + c]);
        float dval = __fadd_rn(t, __fmul_rn(-2.0f, acc));
        unsigned long long key =
            ((unsigned long long)__float_as_uint(dval) << 32) | (unsigned)(k0 + c);
        atomicMin(&g_bestkey[row], key);
    }
}

// ---------------------------------------------------------------------------
// Kernel 6: gather + exact straight-through output + per-row loss partials.
// ---------------------------------------------------------------------------
__global__ void gather_loss_kernel(const float* __restrict__ X,
                                   const float* __restrict__ P,
                                   float* __restrict__ out) {
    int row = blockIdx.x;
    int t = threadIdx.x;
    int c = (int)(unsigned)(g_bestkey[row] & 0xFFFFFFFFull);
    const float* x = X + (size_t)row * D_FIX;
    const float* q = P + (size_t)c * D_FIX;
    float* o = out + (size_t)row * D_FIX;
    double s = 0.0;
#pragma unroll
    for (int i = 0; i < 4; i++) {
        int d = t + i * 128;
        float xv = x[d], qv = q[d];
        float diff = __fsub_rn(qv, xv);
        o[d] = __fadd_rn(xv, diff);
        s += (double)diff * (double)diff;
    }
#pragma unroll
    for (int o2 = 16; o2 > 0; o2 >>= 1) s += __shfl_down_sync(0xffffffffu, s, o2);
    __shared__ double sh[4];
    if ((t & 31) == 0) sh[t >> 5] = s;
    __syncthreads();
    if (t == 0) g_losspart[row] = sh[0] + sh[1] + sh[2] + sh[3];
}

// ---------------------------------------------------------------------------
// Kernel 7a: partial loss sums. 7b: final loss = fl(fl(mse*0.25) + mse).
// ---------------------------------------------------------------------------
__global__ void losssum_kernel() {
    __shared__ double sh[256];
    int t = threadIdx.x;
    sh[t] = g_losspart[blockIdx.x * 256 + t];
    __syncthreads();
    for (int o = 128; o > 0; o >>= 1) {
        if (t < o) sh[t] += sh[t + o];
        __syncthreads();
    }
    if (t == 0) g_losspart2[blockIdx.x] = sh[0];
}

__global__ void finalize_kernel(float* __restrict__ out,
                                long long tail_start, long long out_sz) {
    __shared__ double sh[128];
    int t = threadIdx.x;
    sh[t] = g_losspart2[t];
    __syncthreads();
    for (int o = 64; o > 0; o >>= 1) {
        if (t < o) sh[t] += sh[t + o];
        __syncthreads();
    }
    if (t == 0) {
        double mean = sh[0] / ((double)NR * (double)D_FIX);
        float m = (float)mean;
        float v = __fadd_rn(__fmul_rn(m, 0.25f), m);
        for (long long i = tail_start; i < out_sz; ++i) out[i] = v;
    }
}

// ---------------------------------------------------------------------------
extern "C" void kernel_launch(void* const* d_in, const int* in_sizes, int n_in,
                              void* d_out, int out_size) {
    const float* X = (const float*)d_in[0];
    const float* P = (const float*)d_in[1];
    float* out = (float*)d_out;

    cudaFuncSetAttribute(gemm_gmin_kernel,
                         cudaFuncAttributeMaxDynamicSharedMemorySize, SMEM_TOTAL);

    norms_kernel<<<NR + KP, 128>>>(X, P);    // also inits rowub/bestkey/wcount
    prep_kernel<<<(NR * NCH16 + KP * NCH16) / 256, 256>>>(X, P);
    gemm_gmin_kernel<<<RBLK * CBLK, 256, SMEM_TOTAL>>>();
    flag_kernel<<<NR / 64, 256>>>();
    rescore_kernel<<<1024, 256>>>(X, P);
    gather_loss_kernel<<<NR, 128>>>(X, P, out);
    losssum_kernel<<<128, 256>>>();
    finalize_kernel<<<1, 128>>>(out, (long long)NR * D_FIX, (long long)out_size);
}